// round 6
// baseline (speedup 1.0000x reference)
#include <cuda_runtime.h>
#include <cuda_fp16.h>
#include <cfloat>
#include <cstdint>

// Problem constants
#define B_   32
#define N_   512
#define D_   791
#define H_   7
#define DK_  113
#define M_   (B_ * N_)     // 16384
#define MAXP 64

// main HMMA GEMM geometry: CTA 256x128, warp tile 64x64, 8 warps, 4-stage cp.async
#define KP_     832          // padded K (13 * 64)
#define NPAD_   2432         // fused N = 3*791 = 2373 padded to 19*128
#define STAGE_B 49152        // A 256x64 fp16 (32KB) + B 128x64 fp16 (16KB)
#define GEMM_SMEM (4 * STAGE_B + 256)

// fused attention kernel smem offsets (bytes)
#define AT_OFF_ATTN 0            // 32*512*4    = 65536
#define AT_OFF_K    65536        // 2 * 512*128 = 131072
#define AT_OFF_Q    196608       // 4 * 32*128  = 16384
#define AT_OFF_RMAX 212992       // 32*4*4      = 512
#define AT_OFF_RSUM 213504       // 512
#define AT_SMEM     214016

// ---------------- scratch (device globals; no allocation allowed) -------------
__device__ __align__(256) __half g_Ahi[M_ * KP_];
__device__ __align__(256) __half g_Alo[M_ * KP_];
__device__ __align__(256) __half g_Bh [NPAD_ * KP_];
__device__ __align__(256) __half g_Qhi[(size_t)B_ * H_ * N_ * 128];  // pad dk 113..127 stays 0
__device__ __align__(256) __half g_Qlo[(size_t)B_ * H_ * N_ * 128];
__device__ __align__(256) __half g_Khi[(size_t)B_ * H_ * N_ * 128];
__device__ __align__(256) __half g_Klo[(size_t)B_ * H_ * N_ * 128];
__device__ float g_h[M_ * D_];
__device__ float g_attn[B_ * N_ * N_];
__device__ int   g_pos[B_ * MAXP * 2];
__device__ int   g_cnt[B_];

// ---------------- PTX helpers --------------------------------------------------
__device__ __forceinline__ uint32_t smem_u32(const void* p) {
    uint32_t a;
    asm("{ .reg .u64 t; cvta.to.shared.u64 t, %1; cvt.u32.u64 %0, t; }" : "=r"(a) : "l"(p));
    return a;
}
__device__ __forceinline__ void ldm4(uint32_t& r0, uint32_t& r1, uint32_t& r2,
                                     uint32_t& r3, uint32_t a) {
    asm volatile("ldmatrix.sync.aligned.m8n8.x4.shared.b16 {%0,%1,%2,%3}, [%4];"
                 : "=r"(r0), "=r"(r1), "=r"(r2), "=r"(r3) : "r"(a));
}
__device__ __forceinline__ void mma16816(float* d, const uint32_t* a, const uint32_t* b) {
    asm volatile(
        "mma.sync.aligned.m16n8k16.row.col.f32.f16.f16.f32 "
        "{%0,%1,%2,%3}, {%4,%5,%6,%7}, {%8,%9}, {%0,%1,%2,%3};"
        : "+f"(d[0]), "+f"(d[1]), "+f"(d[2]), "+f"(d[3])
        : "r"(a[0]), "r"(a[1]), "r"(a[2]), "r"(a[3]), "r"(b[0]), "r"(b[1]));
}
__device__ __forceinline__ void cpa16(uint32_t dst, const void* src) {
    asm volatile("cp.async.cg.shared.global [%0], [%1], 16;" :: "r"(dst), "l"(src));
}

// ---------------- split conversions --------------------------------------------
__global__ __launch_bounds__(256) void convA_kernel(
    const float* __restrict__ fuse, __half* __restrict__ Ahi, __half* __restrict__ Alo)
{
    int idx = blockIdx.x * 256 + threadIdx.x;      // over M_*KP_
    if (idx >= M_ * KP_) return;
    int m = idx / KP_, k = idx - m * KP_;
    float x = (k < D_) ? fuse[(size_t)m * D_ + k] : 0.f;
    __half hi = __float2half_rn(x);
    float lo = x - __half2float(hi);
    Ahi[idx] = hi;
    Alo[idx] = __float2half_rn(lo);
}

__global__ __launch_bounds__(256) void convB_kernel(
    const float* __restrict__ Wq, const float* __restrict__ Wk,
    const float* __restrict__ Wgc, __half* __restrict__ Bh)
{
    int idx = blockIdx.x * 256 + threadIdx.x;      // over NPAD_*KP_
    if (idx >= NPAD_ * KP_) return;
    int n = idx / KP_, k = idx - n * KP_;
    float x = 0.f;
    if (n < 3 * D_ && k < D_) {
        const float* W;
        int col;
        if (n < D_)          { W = Wq;  col = n; }
        else if (n < 2 * D_) { W = Wk;  col = n - D_; }
        else                 { W = Wgc; col = n - 2 * D_; }
        x = __ldg(&W[(size_t)k * D_ + col]);       // B[n,k] = W[k,col]
    }
    Bh[idx] = __float2half_rn(x);
}

// ---------------- HMMA fused GEMM + pack epilogue -------------------------------
// C[16384, 2373] (q | k | hidden). N-tiles >= 1664 (pure hidden) skip the lo term.
// Epilogue: q/k cols get bias, fp16 hi/lo split, written into head-padded packed
// layout [B,H,N,128]; hidden cols written fp32.
__device__ __forceinline__ void issue_chunk(
    int cc, int tid, int m0, int nt0, uint32_t sb,
    const __half* __restrict__ Ahi, const __half* __restrict__ Alo,
    const __half* __restrict__ Bh)
{
    const int seg = (cc >= 13);
    const int kk0 = (cc - seg * 13) * 64;
    const __half* As = seg ? Alo : Ahi;
    const uint32_t st = sb + (cc & 3) * STAGE_B;
    #pragma unroll
    for (int it = 0; it < 8; it++) {               // A: 2048 x 16B
        int i = tid + it * 256;
        int r = i >> 3, u = i & 7;
        const __half* src = As + (size_t)(m0 + r) * KP_ + kk0 + u * 8;
        cpa16(st + r * 128 + (((u ^ (r & 7))) << 4), src);
    }
    #pragma unroll
    for (int it = 0; it < 4; it++) {               // B: 1024 x 16B
        int i = tid + it * 256;
        int r = i >> 3, u = i & 7;
        const __half* src = Bh + (size_t)(nt0 + r) * KP_ + kk0 + u * 8;
        cpa16(st + 32768 + r * 128 + (((u ^ (r & 7))) << 4), src);
    }
    asm volatile("cp.async.commit_group;" ::: "memory");
}

__global__ __launch_bounds__(256, 1) void gemm_hmma_kernel(
    const __half* __restrict__ Ahi, const __half* __restrict__ Alo,
    const __half* __restrict__ Bh,
    const float* __restrict__ bq, const float* __restrict__ bk,
    __half* __restrict__ Qhi, __half* __restrict__ Qlo,
    __half* __restrict__ Khi, __half* __restrict__ Klo,
    float* __restrict__ hid)
{
    extern __shared__ char smc[];
    const uint32_t sb = (smem_u32(smc) + 127) & ~127u;
    const int tid = threadIdx.x;
    const int wid = tid >> 5, lane = tid & 31;
    const int m0 = blockIdx.y * 256;
    const int nt0 = blockIdx.x * 128;
    const int nch = (nt0 >= 1664) ? 13 : 26;       // pure-hidden tiles: hi term only

    float acc[4][8][4];
    #pragma unroll
    for (int t = 0; t < 4; t++)
        #pragma unroll
        for (int j = 0; j < 8; j++)
            #pragma unroll
            for (int e = 0; e < 4; e++) acc[t][j][e] = 0.f;

    issue_chunk(0, tid, m0, nt0, sb, Ahi, Alo, Bh);
    issue_chunk(1, tid, m0, nt0, sb, Ahi, Alo, Bh);
    issue_chunk(2, tid, m0, nt0, sb, Ahi, Alo, Bh);

    const int warp_m = wid & 3, warp_n = wid >> 2;
    const int rowinA = (lane & 7) + ((lane >> 3) & 1) * 8;
    const int hbA    = lane >> 4;
    const int rowinB = (lane & 7) + ((lane >> 4) & 1) * 8;
    const int hbB    = (lane >> 3) & 1;

    for (int cc = 0; cc < nch; cc++) {
        const int rem = nch - 1 - cc;
        if (rem >= 2)      asm volatile("cp.async.wait_group 2;" ::: "memory");
        else if (rem == 1) asm volatile("cp.async.wait_group 1;" ::: "memory");
        else               asm volatile("cp.async.wait_group 0;" ::: "memory");
        __syncthreads();
        if (cc + 3 < nch) issue_chunk(cc + 3, tid, m0, nt0, sb, Ahi, Alo, Bh);

        const uint32_t st = sb + (cc & 3) * STAGE_B;
        #pragma unroll
        for (int s = 0; s < 4; s++) {
            uint32_t a[4][4], b[8][2];
            #pragma unroll
            for (int t = 0; t < 4; t++) {
                int r = warp_m * 64 + t * 16 + rowinA;
                uint32_t ad = st + r * 128 + ((((s << 1) | hbA) ^ (r & 7)) << 4);
                ldm4(a[t][0], a[t][1], a[t][2], a[t][3], ad);
            }
            #pragma unroll
            for (int jj = 0; jj < 4; jj++) {
                int r = warp_n * 64 + jj * 16 + rowinB;
                uint32_t ad = st + 32768 + r * 128 + ((((s << 1) | hbB) ^ (r & 7)) << 4);
                ldm4(b[2 * jj][0], b[2 * jj][1], b[2 * jj + 1][0], b[2 * jj + 1][1], ad);
            }
            #pragma unroll
            for (int t = 0; t < 4; t++)
                #pragma unroll
                for (int j = 0; j < 8; j++)
                    mma16816(acc[t][j], a[t], b[j]);
        }
    }

    // epilogue: q/k -> packed fp16 hi/lo [B,H,N,128]; hidden -> fp32
    #pragma unroll
    for (int t = 0; t < 4; t++) {
        const int row0 = m0 + warp_m * 64 + t * 16 + (lane >> 2);
        #pragma unroll
        for (int j = 0; j < 8; j++) {
            const int col = nt0 + warp_n * 64 + j * 8 + (lane & 3) * 2;
            #pragma unroll
            for (int half = 0; half < 2; half++) {
                const int row = half ? (row0 + 8) : row0;
                const int b = row >> 9, n = row & (N_ - 1);
                #pragma unroll
                for (int e = 0; e < 2; e++) {
                    const int c = col + e;
                    float v = acc[t][j][half * 2 + e];
                    if (c < 2 * D_) {
                        __half *Phi, *Plo;
                        int cl;
                        if (c < D_) { cl = c;      v += __ldg(&bq[cl]); Phi = Qhi; Plo = Qlo; }
                        else        { cl = c - D_; v += __ldg(&bk[cl]); Phi = Khi; Plo = Klo; }
                        const int h = cl / DK_;
                        const int dk = cl - h * DK_;
                        const size_t dst = (((size_t)(b * H_ + h) * N_ + n) << 7) + dk;
                        __half hiv = __float2half_rn(v);
                        Phi[dst] = hiv;
                        Plo[dst] = __float2half_rn(v - __half2float(hiv));
                    } else if (c < 3 * D_) {
                        hid[(size_t)row * D_ + (c - 2 * D_)] = v;
                    }
                }
            }
        }
    }
}

// ---------------- fused attention: score GEMM + softmax + head-sum --------------
// CTA: 32 q-rows of one batch. Loops 7 heads x 3 split terms (qhi*khi, qlo*khi,
// qhi*klo). Scores in regs; per-head softmax via smem reductions; attn acc in smem.
// 42 steps total; step s: head=s/6, term=(s%6)>>1, kc=s&1. K double-buffered.
__device__ __forceinline__ void at_issue(
    int s, int tid, int b, int n0,
    uint32_t kbase, uint32_t qbase,
    const __half* __restrict__ Qhi, const __half* __restrict__ Qlo,
    const __half* __restrict__ Khi, const __half* __restrict__ Klo)
{
    if (s < 42) {
        const int head = s / 6;
        const int term = (s % 6) >> 1;
        const int kc = s & 1;
        const size_t bhbase = (size_t)(b * H_ + head) * N_ * 128;
        if (term != 1) {                           // load K (khi for t0, klo for t2)
            const __half* Ks = (term == 2) ? Klo : Khi;
            const uint32_t kst = kbase + kc * 65536;
            #pragma unroll
            for (int it = 0; it < 16; it++) {      // 512 rows x 128B
                int i = tid + it * 256;
                int r = i >> 3, u = i & 7;
                const __half* src = Ks + bhbase + (size_t)r * 128 + kc * 64 + u * 8;
                cpa16(kst + r * 128 + ((u ^ (r & 7)) << 4), src);
            }
        }
        if ((s % 6) == 0) {                        // load Q (all 4 sub-buffers)
            #pragma unroll
            for (int it = 0; it < 4; it++) {       // 1024 x 16B
                int i = tid + it * 256;
                int u = i & 7, r = (i >> 3) & 31, qkc = (i >> 8) & 1, qt = i >> 9;
                const __half* Qs = qt ? Qlo : Qhi;
                const __half* src = Qs + bhbase + (size_t)(n0 + r) * 128 + qkc * 64 + u * 8;
                cpa16(qbase + (qt * 2 + qkc) * 4096 + r * 128 + ((u ^ (r & 7)) << 4), src);
            }
        }
    }
    asm volatile("cp.async.commit_group;" ::: "memory");
}

__global__ __launch_bounds__(256, 1) void attn_fused_kernel(
    const __half* __restrict__ Qhi, const __half* __restrict__ Qlo,
    const __half* __restrict__ Khi, const __half* __restrict__ Klo,
    float* __restrict__ attn)
{
    extern __shared__ char smc[];
    const uint32_t sb = smem_u32(smc);
    float* attn_s = (float*)(smc + AT_OFF_ATTN);   // [32][512]
    float* redmax = (float*)(smc + AT_OFF_RMAX);   // [32][4]
    float* redsum = (float*)(smc + AT_OFF_RSUM);   // [32][4]
    const uint32_t kbase = sb + AT_OFF_K;
    const uint32_t qbase = sb + AT_OFF_Q;

    const int tid = threadIdx.x;
    const int wid = tid >> 5, lane = tid & 31;
    const int b = blockIdx.y;
    const int n0 = blockIdx.x * 32;
    const int warp_m = wid & 1, warp_n = wid >> 1;

    for (int i = tid; i < 32 * N_; i += 256) attn_s[i] = 0.f;

    const int rowinA = (lane & 7) + ((lane >> 3) & 1) * 8;
    const int hbA    = lane >> 4;
    const int rowinB = (lane & 7) + ((lane >> 4) & 1) * 8;
    const int hbB    = (lane >> 3) & 1;
    const float scale = rsqrtf((float)DK_);

    const int row0 = warp_m * 16 + (lane >> 2);    // local rows this thread owns
    const int row1 = row0 + 8;

    float sc[16][4];

    at_issue(0, tid, b, n0, kbase, qbase, Qhi, Qlo, Khi, Klo);
    at_issue(1, tid, b, n0, kbase, qbase, Qhi, Qlo, Khi, Klo);

    for (int s = 0; s < 42; s++) {
        if (s == 41) asm volatile("cp.async.wait_group 0;" ::: "memory");
        else         asm volatile("cp.async.wait_group 1;" ::: "memory");
        __syncthreads();

        const int sm6 = s % 6;
        const int term = sm6 >> 1;
        const int kc = s & 1;
        if (sm6 == 0) {
            #pragma unroll
            for (int t = 0; t < 16; t++)
                #pragma unroll
                for (int e = 0; e < 4; e++) sc[t][e] = 0.f;
        }

        const uint32_t kst = kbase + kc * 65536;
        const uint32_t qst = qbase + (((term == 1) ? 1 : 0) * 2 + kc) * 4096;
        #pragma unroll
        for (int s4 = 0; s4 < 4; s4++) {
            uint32_t a[4];
            {
                int r = warp_m * 16 + rowinA;
                uint32_t ad = qst + r * 128 + ((((s4 << 1) | hbA) ^ (r & 7)) << 4);
                ldm4(a[0], a[1], a[2], a[3], ad);
            }
            #pragma unroll
            for (int jj = 0; jj < 8; jj++) {
                uint32_t bb[2][2];
                int r = warp_n * 128 + jj * 16 + rowinB;
                uint32_t ad = kst + r * 128 + ((((s4 << 1) | hbB) ^ (r & 7)) << 4);
                ldm4(bb[0][0], bb[0][1], bb[1][0], bb[1][1], ad);
                mma16816(sc[2 * jj],     a, bb[0]);
                mma16816(sc[2 * jj + 1], a, bb[1]);
            }
        }
        __syncthreads();                            // all warps done with buffers
        at_issue(s + 2, tid, b, n0, kbase, qbase, Qhi, Qlo, Khi, Klo);

        if (sm6 == 5) {
            // ---- softmax over this head's 512 cols, accumulate into attn_s ----
            #pragma unroll
            for (int t = 0; t < 16; t++)
                #pragma unroll
                for (int e = 0; e < 4; e++) sc[t][e] *= scale;

            float m0 = -FLT_MAX, m1 = -FLT_MAX;
            #pragma unroll
            for (int t = 0; t < 16; t++) {
                m0 = fmaxf(m0, fmaxf(sc[t][0], sc[t][1]));
                m1 = fmaxf(m1, fmaxf(sc[t][2], sc[t][3]));
            }
            m0 = fmaxf(m0, __shfl_xor_sync(0xFFFFFFFFu, m0, 1));
            m0 = fmaxf(m0, __shfl_xor_sync(0xFFFFFFFFu, m0, 2));
            m1 = fmaxf(m1, __shfl_xor_sync(0xFFFFFFFFu, m1, 1));
            m1 = fmaxf(m1, __shfl_xor_sync(0xFFFFFFFFu, m1, 2));
            if ((lane & 3) == 0) {
                redmax[row0 * 4 + warp_n] = m0;
                redmax[row1 * 4 + warp_n] = m1;
            }
            __syncthreads();
            float M0 = fmaxf(fmaxf(redmax[row0 * 4], redmax[row0 * 4 + 1]),
                             fmaxf(redmax[row0 * 4 + 2], redmax[row0 * 4 + 3]));
            float M1 = fmaxf(fmaxf(redmax[row1 * 4], redmax[row1 * 4 + 1]),
                             fmaxf(redmax[row1 * 4 + 2], redmax[row1 * 4 + 3]));
            float s0 = 0.f, s1 = 0.f;
            #pragma unroll
            for (int t = 0; t < 16; t++) {
                sc[t][0] = __expf(sc[t][0] - M0);
                sc[t][1] = __expf(sc[t][1] - M0);
                sc[t][2] = __expf(sc[t][2] - M1);
                sc[t][3] = __expf(sc[t][3] - M1);
                s0 += sc[t][0] + sc[t][1];
                s1 += sc[t][2] + sc[t][3];
            }
            s0 += __shfl_xor_sync(0xFFFFFFFFu, s0, 1);
            s0 += __shfl_xor_sync(0xFFFFFFFFu, s0, 2);
            s1 += __shfl_xor_sync(0xFFFFFFFFu, s1, 1);
            s1 += __shfl_xor_sync(0xFFFFFFFFu, s1, 2);
            if ((lane & 3) == 0) {
                redsum[row0 * 4 + warp_n] = s0;
                redsum[row1 * 4 + warp_n] = s1;
            }
            __syncthreads();
            float inv0 = __frcp_rn(redsum[row0 * 4] + redsum[row0 * 4 + 1] +
                                   redsum[row0 * 4 + 2] + redsum[row0 * 4 + 3]);
            float inv1 = __frcp_rn(redsum[row1 * 4] + redsum[row1 * 4 + 1] +
                                   redsum[row1 * 4 + 2] + redsum[row1 * 4 + 3]);
            float* a0 = attn_s + row0 * N_ + warp_n * 128 + (lane & 3) * 2;
            float* a1 = attn_s + row1 * N_ + warp_n * 128 + (lane & 3) * 2;
            #pragma unroll
            for (int t = 0; t < 16; t++) {
                a0[t * 8]     += sc[t][0] * inv0;
                a0[t * 8 + 1] += sc[t][1] * inv0;
                a1[t * 8]     += sc[t][2] * inv1;
                a1[t * 8 + 1] += sc[t][3] * inv1;
            }
            __syncthreads();                        // red bufs reused next head
        }
    }

    for (int i = tid; i < 32 * N_; i += 256) {
        int r = i >> 9, m = i & (N_ - 1);
        attn[((size_t)b * N_ + n0 + r) * N_ + m] = attn_s[i];
    }
}

// ---------------- per-batch top-2 threshold + positions -------------------------
__global__ __launch_bounds__(256) void top2_kernel(
    const float* __restrict__ attn, int* __restrict__ pos, int* __restrict__ cnt)
{
    __shared__ float v1s[256], v2s[256];
    __shared__ float s_kth;
    __shared__ int   s_cnt;

    const int b = blockIdx.x;
    const int tid = threadIdx.x;
    const float* A = attn + (size_t)b * N_ * N_;

    float v1 = -FLT_MAX, v2 = -FLT_MAX;
    for (int i = tid; i < N_ * N_; i += 256) {
        float v = A[i];
        if (v > v1) { v2 = v1; v1 = v; }
        else if (v > v2) v2 = v;
    }
    v1s[tid] = v1; v2s[tid] = v2;
    __syncthreads();
    if (tid == 0) {
        float t1 = -FLT_MAX, t2 = -FLT_MAX;
        for (int i = 0; i < 256; i++) {
            float a = v1s[i], c = v2s[i];
            if (a > t1) { t2 = t1; t1 = a; } else if (a > t2) t2 = a;
            if (c > t1) { t2 = t1; t1 = c; } else if (c > t2) t2 = c;
        }
        s_kth = t2;
        s_cnt = 0;
    }
    __syncthreads();
    const float kth = s_kth;
    const int base = b * MAXP * 2;
    for (int i = tid; i < N_ * N_; i += 256) {
        if (A[i] >= kth) {
            int idx = atomicAdd(&s_cnt, 1);
            if (idx < MAXP) {
                pos[base + idx * 2]     = i >> 9;
                pos[base + idx * 2 + 1] = i & (N_ - 1);
            }
        }
    }
    __syncthreads();
    if (tid == 0) {
        int c = s_cnt < MAXP ? s_cnt : MAXP;
        for (int a2 = 1; a2 < c; a2++) {
            int ki = pos[base + a2 * 2], kj = pos[base + a2 * 2 + 1];
            int key = ki * N_ + kj;
            int p = a2 - 1;
            while (p >= 0) {
                int pi = pos[base + p * 2], pj = pos[base + p * 2 + 1];
                if (pi * N_ + pj <= key) break;
                pos[base + (p + 1) * 2] = pi;
                pos[base + (p + 1) * 2 + 1] = pj;
                p--;
            }
            pos[base + (p + 1) * 2] = ki;
            pos[base + (p + 1) * 2 + 1] = kj;
        }
        cnt[b] = c;
    }
}

// ---------------- sparse adjacency apply + GC epilogue --------------------------
__global__ __launch_bounds__(256) void out_kernel(
    const float* __restrict__ attn, const float* __restrict__ hidden,
    const float* __restrict__ bgc, const int* __restrict__ pos,
    const int* __restrict__ cnt, float* __restrict__ out)
{
    const int b = blockIdx.y;
    const int n = blockIdx.x;
    const int tid = threadIdx.x;

    __shared__ int   s_nc;
    __shared__ int   s_cols[2 * MAXP];
    __shared__ float s_w[2 * MAXP];
    __shared__ float s_wd, s_inv;

    if (tid == 0) {
        const float* An = attn + ((size_t)b * N_ + n) * N_;
        const int base = b * MAXP * 2;
        int c = cnt[b];
        int nc = 0;
        float wd = An[n];
        float sum = wd;
        for (int e = 0; e < c; e++) {
            int i = pos[base + e * 2], j = pos[base + e * 2 + 1];
            if (i == n && j != n) { float w = An[j]; s_cols[nc] = j; s_w[nc] = w; sum += w; nc++; }
            if (j == n && i != n) { float w = An[i]; s_cols[nc] = i; s_w[nc] = w; sum += w; nc++; }
        }
        s_nc = nc; s_wd = wd; s_inv = 1.f / (sum + 1.f);
    }
    __syncthreads();

    const int nc = s_nc;
    const float wd = s_wd, inv = s_inv;
    const float* hn = hidden + ((size_t)b * N_ + n) * D_;
    float* on = out + ((size_t)b * N_ + n) * D_;

    for (int d = tid; d < D_; d += 256) {
        float v = wd * hn[d];
        for (int e = 0; e < nc; e++)
            v += s_w[e] * hidden[((size_t)b * N_ + s_cols[e]) * D_ + d];
        v = v * inv + __ldg(&bgc[d]);
        on[d] = fmaxf(v, 0.f);
    }
}

// ---------------- launch ------------------------------------------------------
extern "C" void kernel_launch(void* const* d_in, const int* in_sizes, int n_in,
                              void* d_out, int out_size)
{
    const float* fuse = (const float*)d_in[0];
    const float* Wq   = (const float*)d_in[1];
    const float* bq   = (const float*)d_in[2];
    const float* Wk   = (const float*)d_in[3];
    const float* bk   = (const float*)d_in[4];
    const float* Wgc  = (const float*)d_in[5];
    const float* bgc  = (const float*)d_in[6];
    float* out = (float*)d_out;

    __half *Ahi, *Alo, *Bh, *Qhi, *Qlo, *Khi, *Klo;
    float *hid, *attn;
    int *pos, *cnt;
    cudaGetSymbolAddress((void**)&Ahi,  g_Ahi);
    cudaGetSymbolAddress((void**)&Alo,  g_Alo);
    cudaGetSymbolAddress((void**)&Bh,   g_Bh);
    cudaGetSymbolAddress((void**)&Qhi,  g_Qhi);
    cudaGetSymbolAddress((void**)&Qlo,  g_Qlo);
    cudaGetSymbolAddress((void**)&Khi,  g_Khi);
    cudaGetSymbolAddress((void**)&Klo,  g_Klo);
    cudaGetSymbolAddress((void**)&hid,  g_h);
    cudaGetSymbolAddress((void**)&attn, g_attn);
    cudaGetSymbolAddress((void**)&pos,  g_pos);
    cudaGetSymbolAddress((void**)&cnt,  g_cnt);

    // 0) fp16 hi/lo split of A (fuse) and fp16 fused-transposed B (Wq|Wk|Wgc)
    convA_kernel<<<(M_ * KP_ + 255) / 256, 256>>>(fuse, Ahi, Alo);
    convB_kernel<<<(NPAD_ * KP_ + 255) / 256, 256>>>(Wq, Wk, Wgc, Bh);

    // 1) fused HMMA GEMM -> packed q/k (fp16 hi/lo) + hidden (fp32)
    cudaFuncSetAttribute(gemm_hmma_kernel, cudaFuncAttributeMaxDynamicSharedMemorySize, GEMM_SMEM);
    gemm_hmma_kernel<<<dim3(NPAD_ / 128, M_ / 256), 256, GEMM_SMEM>>>(
        Ahi, Alo, Bh, bq, bk, Qhi, Qlo, Khi, Klo, hid);

    // 2) fused score GEMM + softmax + head-sum -> attn
    cudaFuncSetAttribute(attn_fused_kernel, cudaFuncAttributeMaxDynamicSharedMemorySize, AT_SMEM);
    attn_fused_kernel<<<dim3(N_ / 32, B_), 256, AT_SMEM>>>(Qhi, Qlo, Khi, Klo, attn);

    // 3) per-batch top-2 threshold + sparse positions
    top2_kernel<<<B_, 256>>>(attn, pos, cnt);

    // 4) sparse adjacency apply + graph-conv epilogue
    out_kernel<<<dim3(N_, B_), 256>>>(attn, hid, bgc, pos, cnt, out);
}

// round 7
// speedup vs baseline: 1.0251x; 1.0251x over previous
#include <cuda_runtime.h>
#include <cuda_fp16.h>
#include <cfloat>
#include <cstdint>

// Problem constants
#define B_   32
#define N_   512
#define D_   791
#define H_   7
#define DK_  113
#define M_   (B_ * N_)     // 16384
#define MAXP 64

// main HMMA GEMM geometry: CTA 256x128, warp tile 64x64, 8 warps, 4-stage cp.async
#define KP_     832          // padded K (13 * 64)
#define NPAD_   2432         // fused N = 3*791 = 2373 padded to 19*128
#define STAGE_B 49152        // A 256x64 fp16 (32KB) + B 128x64 fp16 (16KB)
#define GEMM_SMEM (4 * STAGE_B + 256)
#define BHN (B_ * H_ * N_)   // 114688 packed rows

// fused attention kernel smem offsets (bytes), 512 threads / 16 warps
#define AT_OFF_ATTN 0            // 32*512*4    = 65536
#define AT_OFF_K    65536        // 2 * 512*128 = 131072
#define AT_OFF_Q    196608       // 4 * 32*128  = 16384
#define AT_OFF_RMAX 212992       // 32*8*4      = 1024
#define AT_OFF_RSUM 214016       // 1024
#define AT_SMEM     215040

// ---------------- scratch (device globals; no allocation allowed) -------------
__device__ __align__(256) __half g_Ahi[M_ * KP_];
__device__ __align__(256) __half g_Alo[M_ * KP_];
__device__ __align__(256) __half g_Bh [NPAD_ * KP_];
__device__ __align__(256) __half g_Qhi[(size_t)BHN * 128];
__device__ __align__(256) __half g_Qlo[(size_t)BHN * 128];
__device__ __align__(256) __half g_Khi[(size_t)BHN * 128];
__device__ __align__(256) __half g_Klo[(size_t)BHN * 128];
__device__ float g_q[M_ * D_];
__device__ float g_k[M_ * D_];
__device__ float g_h[M_ * D_];
__device__ float g_attn[B_ * N_ * N_];
__device__ int   g_pos[B_ * MAXP * 2];
__device__ int   g_cnt[B_];

// ---------------- PTX helpers --------------------------------------------------
__device__ __forceinline__ uint32_t smem_u32(const void* p) {
    uint32_t a;
    asm("{ .reg .u64 t; cvta.to.shared.u64 t, %1; cvt.u32.u64 %0, t; }" : "=r"(a) : "l"(p));
    return a;
}
__device__ __forceinline__ void ldm4(uint32_t& r0, uint32_t& r1, uint32_t& r2,
                                     uint32_t& r3, uint32_t a) {
    asm volatile("ldmatrix.sync.aligned.m8n8.x4.shared.b16 {%0,%1,%2,%3}, [%4];"
                 : "=r"(r0), "=r"(r1), "=r"(r2), "=r"(r3) : "r"(a));
}
__device__ __forceinline__ void mma16816(float* d, const uint32_t* a, const uint32_t* b) {
    asm volatile(
        "mma.sync.aligned.m16n8k16.row.col.f32.f16.f16.f32 "
        "{%0,%1,%2,%3}, {%4,%5,%6,%7}, {%8,%9}, {%0,%1,%2,%3};"
        : "+f"(d[0]), "+f"(d[1]), "+f"(d[2]), "+f"(d[3])
        : "r"(a[0]), "r"(a[1]), "r"(a[2]), "r"(a[3]), "r"(b[0]), "r"(b[1]));
}
__device__ __forceinline__ void cpa16(uint32_t dst, const void* src) {
    asm volatile("cp.async.cg.shared.global [%0], [%1], 16;" :: "r"(dst), "l"(src));
}

// ---------------- split conversions --------------------------------------------
__global__ __launch_bounds__(256) void convA_kernel(
    const float* __restrict__ fuse, __half* __restrict__ Ahi, __half* __restrict__ Alo)
{
    int idx = blockIdx.x * 256 + threadIdx.x;      // over M_*KP_
    if (idx >= M_ * KP_) return;
    int m = idx / KP_, k = idx - m * KP_;
    float x = (k < D_) ? fuse[(size_t)m * D_ + k] : 0.f;
    __half hi = __float2half_rn(x);
    float lo = x - __half2float(hi);
    Ahi[idx] = hi;
    Alo[idx] = __float2half_rn(lo);
}

__global__ __launch_bounds__(256) void convB_kernel(
    const float* __restrict__ Wq, const float* __restrict__ Wk,
    const float* __restrict__ Wgc, __half* __restrict__ Bh)
{
    int idx = blockIdx.x * 256 + threadIdx.x;      // over NPAD_*KP_
    if (idx >= NPAD_ * KP_) return;
    int n = idx / KP_, k = idx - n * KP_;
    float x = 0.f;
    if (n < 3 * D_ && k < D_) {
        const float* W;
        int col;
        if (n < D_)          { W = Wq;  col = n; }
        else if (n < 2 * D_) { W = Wk;  col = n - D_; }
        else                 { W = Wgc; col = n - 2 * D_; }
        x = __ldg(&W[(size_t)k * D_ + col]);       // B[n,k] = W[k,col]
    }
    Bh[idx] = __float2half_rn(x);
}

// ---------------- HMMA fused GEMM ----------------------------------------------
// C[16384, 2373] (q | k | hidden). N-tiles >= 1664 (pure hidden) skip the lo term.
__device__ __forceinline__ void issue_chunk(
    int cc, int tid, int m0, int nt0, uint32_t sb,
    const __half* __restrict__ Ahi, const __half* __restrict__ Alo,
    const __half* __restrict__ Bh)
{
    const int seg = (cc >= 13);
    const int kk0 = (cc - seg * 13) * 64;
    const __half* As = seg ? Alo : Ahi;
    const uint32_t st = sb + (cc & 3) * STAGE_B;
    #pragma unroll
    for (int it = 0; it < 8; it++) {               // A: 2048 x 16B
        int i = tid + it * 256;
        int r = i >> 3, u = i & 7;
        const __half* src = As + (size_t)(m0 + r) * KP_ + kk0 + u * 8;
        cpa16(st + r * 128 + (((u ^ (r & 7))) << 4), src);
    }
    #pragma unroll
    for (int it = 0; it < 4; it++) {               // B: 1024 x 16B
        int i = tid + it * 256;
        int r = i >> 3, u = i & 7;
        const __half* src = Bh + (size_t)(nt0 + r) * KP_ + kk0 + u * 8;
        cpa16(st + 32768 + r * 128 + (((u ^ (r & 7))) << 4), src);
    }
    asm volatile("cp.async.commit_group;" ::: "memory");
}

__global__ __launch_bounds__(256, 1) void gemm_hmma_kernel(
    const __half* __restrict__ Ahi, const __half* __restrict__ Alo,
    const __half* __restrict__ Bh,
    const float* __restrict__ bq, const float* __restrict__ bk,
    float* __restrict__ q, float* __restrict__ kk, float* __restrict__ hid)
{
    extern __shared__ char smc[];
    const uint32_t sb = (smem_u32(smc) + 127) & ~127u;
    const int tid = threadIdx.x;
    const int wid = tid >> 5, lane = tid & 31;
    const int m0 = blockIdx.y * 256;
    const int nt0 = blockIdx.x * 128;
    const int nch = (nt0 >= 1664) ? 13 : 26;       // pure-hidden tiles: hi term only

    float acc[4][8][4];
    #pragma unroll
    for (int t = 0; t < 4; t++)
        #pragma unroll
        for (int j = 0; j < 8; j++)
            #pragma unroll
            for (int e = 0; e < 4; e++) acc[t][j][e] = 0.f;

    issue_chunk(0, tid, m0, nt0, sb, Ahi, Alo, Bh);
    issue_chunk(1, tid, m0, nt0, sb, Ahi, Alo, Bh);
    issue_chunk(2, tid, m0, nt0, sb, Ahi, Alo, Bh);

    const int warp_m = wid & 3, warp_n = wid >> 2;
    const int rowinA = (lane & 7) + ((lane >> 3) & 1) * 8;
    const int hbA    = lane >> 4;
    const int rowinB = (lane & 7) + ((lane >> 4) & 1) * 8;
    const int hbB    = (lane >> 3) & 1;

    for (int cc = 0; cc < nch; cc++) {
        const int rem = nch - 1 - cc;
        if (rem >= 2)      asm volatile("cp.async.wait_group 2;" ::: "memory");
        else if (rem == 1) asm volatile("cp.async.wait_group 1;" ::: "memory");
        else               asm volatile("cp.async.wait_group 0;" ::: "memory");
        __syncthreads();
        if (cc + 3 < nch) issue_chunk(cc + 3, tid, m0, nt0, sb, Ahi, Alo, Bh);

        const uint32_t st = sb + (cc & 3) * STAGE_B;
        #pragma unroll
        for (int s = 0; s < 4; s++) {
            uint32_t a[4][4], b[8][2];
            #pragma unroll
            for (int t = 0; t < 4; t++) {
                int r = warp_m * 64 + t * 16 + rowinA;
                uint32_t ad = st + r * 128 + ((((s << 1) | hbA) ^ (r & 7)) << 4);
                ldm4(a[t][0], a[t][1], a[t][2], a[t][3], ad);
            }
            #pragma unroll
            for (int jj = 0; jj < 4; jj++) {
                int r = warp_n * 64 + jj * 16 + rowinB;
                uint32_t ad = st + 32768 + r * 128 + ((((s << 1) | hbB) ^ (r & 7)) << 4);
                ldm4(b[2 * jj][0], b[2 * jj][1], b[2 * jj + 1][0], b[2 * jj + 1][1], ad);
            }
            #pragma unroll
            for (int t = 0; t < 4; t++)
                #pragma unroll
                for (int j = 0; j < 8; j++)
                    mma16816(acc[t][j], a[t], b[j]);
        }
    }

    // epilogue: demux to q | k | hid with bias (contiguous fp32 stores)
    #pragma unroll
    for (int t = 0; t < 4; t++) {
        const int row0 = m0 + warp_m * 64 + t * 16 + (lane >> 2);
        #pragma unroll
        for (int j = 0; j < 8; j++) {
            const int col = nt0 + warp_n * 64 + j * 8 + (lane & 3) * 2;
            #pragma unroll
            for (int half = 0; half < 2; half++) {
                const int row = row0 + half * 8;
                const float v0 = acc[t][j][half * 2];
                const float v1 = acc[t][j][half * 2 + 1];
                #pragma unroll
                for (int e = 0; e < 2; e++) {
                    const int c = col + e;
                    const float v = e ? v1 : v0;
                    if (c < D_)
                        q[(size_t)row * D_ + c] = v + __ldg(&bq[c]);
                    else if (c < 2 * D_)
                        kk[(size_t)row * D_ + (c - D_)] = v + __ldg(&bk[c - D_]);
                    else if (c < 3 * D_)
                        hid[(size_t)row * D_ + (c - 2 * D_)] = v;
                }
            }
        }
    }
}

// ---------------- pack q/k into head-padded fp16 hi/lo --------------------------
__global__ __launch_bounds__(256) void pack_qk_kernel(
    const float* __restrict__ q, const float* __restrict__ k,
    __half* __restrict__ Qhi, __half* __restrict__ Qlo,
    __half* __restrict__ Khi, __half* __restrict__ Klo)
{
    int idx = blockIdx.x * 256 + threadIdx.x;      // over BHN*128
    if (idx >= BHN * 128) return;
    int dk = idx & 127;
    int rest = idx >> 7;
    int n = rest & (N_ - 1);
    int bh = rest >> 9;
    int h = bh % H_, b = bh / H_;
    float qv = 0.f, kv = 0.f;
    if (dk < DK_) {
        size_t off = ((size_t)(b * N_ + n)) * D_ + h * DK_ + dk;
        qv = q[off];
        kv = k[off];
    }
    __half qh = __float2half_rn(qv);
    __half kh = __float2half_rn(kv);
    Qhi[idx] = qh;
    Qlo[idx] = __float2half_rn(qv - __half2float(qh));
    Khi[idx] = kh;
    Klo[idx] = __float2half_rn(kv - __half2float(kh));
}

// ---------------- fused attention: score GEMM + softmax + head-sum --------------
// CTA: 32 q-rows of one batch, 512 threads / 16 warps (2m x 8n), warp tile 16x64.
// 42 steps; step s: head=s/6, term=(s%6)>>1 (qhi*khi, qlo*khi, qhi*klo), kc=s&1.
__device__ __forceinline__ void at_issue(
    int s, int tid, int b, int n0,
    uint32_t kbase, uint32_t qbase,
    const __half* __restrict__ Qhi, const __half* __restrict__ Qlo,
    const __half* __restrict__ Khi, const __half* __restrict__ Klo)
{
    if (s < 42) {
        const int head = s / 6;
        const int term = (s % 6) >> 1;
        const int kc = s & 1;
        const size_t bhbase = (size_t)(b * H_ + head) * N_ * 128;
        if (term != 1) {                           // load K (khi for t0, klo for t2)
            const __half* Ks = (term == 2) ? Klo : Khi;
            const uint32_t kst = kbase + kc * 65536;
            #pragma unroll
            for (int it = 0; it < 8; it++) {       // 512 rows x 128B = 4096 x 16B
                int i = tid + it * 512;
                int r = i >> 3, u = i & 7;
                const __half* src = Ks + bhbase + (size_t)r * 128 + kc * 64 + u * 8;
                cpa16(kst + r * 128 + ((u ^ (r & 7)) << 4), src);
            }
        }
        if ((s % 6) == 0) {                        // load Q (all 4 sub-buffers)
            #pragma unroll
            for (int it = 0; it < 2; it++) {       // 1024 x 16B
                int i = tid + it * 512;
                int u = i & 7, r = (i >> 3) & 31, qkc = (i >> 8) & 1, qt = i >> 9;
                const __half* Qs = qt ? Qlo : Qhi;
                const __half* src = Qs + bhbase + (size_t)(n0 + r) * 128 + qkc * 64 + u * 8;
                cpa16(qbase + (qt * 2 + qkc) * 4096 + r * 128 + ((u ^ (r & 7)) << 4), src);
            }
        }
    }
    asm volatile("cp.async.commit_group;" ::: "memory");
}

__global__ __launch_bounds__(512, 1) void attn_fused_kernel(
    const __half* __restrict__ Qhi, const __half* __restrict__ Qlo,
    const __half* __restrict__ Khi, const __half* __restrict__ Klo,
    float* __restrict__ attn)
{
    extern __shared__ char smc[];
    const uint32_t sb = smem_u32(smc);
    float* attn_s = (float*)(smc + AT_OFF_ATTN);   // [32][512]
    float* redmax = (float*)(smc + AT_OFF_RMAX);   // [32][8]
    float* redsum = (float*)(smc + AT_OFF_RSUM);   // [32][8]
    const uint32_t kbase = sb + AT_OFF_K;
    const uint32_t qbase = sb + AT_OFF_Q;

    const int tid = threadIdx.x;
    const int wid = tid >> 5, lane = tid & 31;
    const int b = blockIdx.y;
    const int n0 = blockIdx.x * 32;
    const int warp_m = wid & 1, warp_n = wid >> 1;    // 2 x 8

    for (int i = tid; i < 32 * N_; i += 512) attn_s[i] = 0.f;

    const int rowinA = (lane & 7) + ((lane >> 3) & 1) * 8;
    const int hbA    = lane >> 4;
    const int rowinB = (lane & 7) + ((lane >> 4) & 1) * 8;
    const int hbB    = (lane >> 3) & 1;
    const float scale = rsqrtf((float)DK_);

    const int row0 = warp_m * 16 + (lane >> 2);    // local rows this thread owns
    const int row1 = row0 + 8;

    float sc[8][4];                                 // 8 n8-tiles x 4 elems

    at_issue(0, tid, b, n0, kbase, qbase, Qhi, Qlo, Khi, Klo);
    at_issue(1, tid, b, n0, kbase, qbase, Qhi, Qlo, Khi, Klo);

    for (int s = 0; s < 42; s++) {
        if (s == 41) asm volatile("cp.async.wait_group 0;" ::: "memory");
        else         asm volatile("cp.async.wait_group 1;" ::: "memory");
        __syncthreads();

        const int sm6 = s % 6;
        const int term = sm6 >> 1;
        const int kc = s & 1;
        if (sm6 == 0) {
            #pragma unroll
            for (int t = 0; t < 8; t++)
                #pragma unroll
                for (int e = 0; e < 4; e++) sc[t][e] = 0.f;
        }

        const uint32_t kst = kbase + kc * 65536;
        const uint32_t qst = qbase + (((term == 1) ? 1 : 0) * 2 + kc) * 4096;
        #pragma unroll
        for (int s4 = 0; s4 < 4; s4++) {
            uint32_t a[4];
            {
                int r = warp_m * 16 + rowinA;
                uint32_t ad = qst + r * 128 + ((((s4 << 1) | hbA) ^ (r & 7)) << 4);
                ldm4(a[0], a[1], a[2], a[3], ad);
            }
            #pragma unroll
            for (int jj = 0; jj < 4; jj++) {
                uint32_t bb[2][2];
                int r = warp_n * 64 + jj * 16 + rowinB;
                uint32_t ad = kst + r * 128 + ((((s4 << 1) | hbB) ^ (r & 7)) << 4);
                ldm4(bb[0][0], bb[0][1], bb[1][0], bb[1][1], ad);
                mma16816(sc[2 * jj],     a, bb[0]);
                mma16816(sc[2 * jj + 1], a, bb[1]);
            }
        }
        __syncthreads();                            // all warps done with buffers
        at_issue(s + 2, tid, b, n0, kbase, qbase, Qhi, Qlo, Khi, Klo);

        if (sm6 == 5) {
            // ---- softmax over this head's 512 cols, accumulate into attn_s ----
            #pragma unroll
            for (int t = 0; t < 8; t++)
                #pragma unroll
                for (int e = 0; e < 4; e++) sc[t][e] *= scale;

            float m0 = -FLT_MAX, m1 = -FLT_MAX;
            #pragma unroll
            for (int t = 0; t < 8; t++) {
                m0 = fmaxf(m0, fmaxf(sc[t][0], sc[t][1]));
                m1 = fmaxf(m1, fmaxf(sc[t][2], sc[t][3]));
            }
            m0 = fmaxf(m0, __shfl_xor_sync(0xFFFFFFFFu, m0, 1));
            m0 = fmaxf(m0, __shfl_xor_sync(0xFFFFFFFFu, m0, 2));
            m1 = fmaxf(m1, __shfl_xor_sync(0xFFFFFFFFu, m1, 1));
            m1 = fmaxf(m1, __shfl_xor_sync(0xFFFFFFFFu, m1, 2));
            if ((lane & 3) == 0) {
                redmax[row0 * 8 + warp_n] = m0;
                redmax[row1 * 8 + warp_n] = m1;
            }
            __syncthreads();
            float M0 = -FLT_MAX, M1 = -FLT_MAX;
            #pragma unroll
            for (int w = 0; w < 8; w++) {
                M0 = fmaxf(M0, redmax[row0 * 8 + w]);
                M1 = fmaxf(M1, redmax[row1 * 8 + w]);
            }
            float s0 = 0.f, s1 = 0.f;
            #pragma unroll
            for (int t = 0; t < 8; t++) {
                sc[t][0] = __expf(sc[t][0] - M0);
                sc[t][1] = __expf(sc[t][1] - M0);
                sc[t][2] = __expf(sc[t][2] - M1);
                sc[t][3] = __expf(sc[t][3] - M1);
                s0 += sc[t][0] + sc[t][1];
                s1 += sc[t][2] + sc[t][3];
            }
            s0 += __shfl_xor_sync(0xFFFFFFFFu, s0, 1);
            s0 += __shfl_xor_sync(0xFFFFFFFFu, s0, 2);
            s1 += __shfl_xor_sync(0xFFFFFFFFu, s1, 1);
            s1 += __shfl_xor_sync(0xFFFFFFFFu, s1, 2);
            if ((lane & 3) == 0) {
                redsum[row0 * 8 + warp_n] = s0;
                redsum[row1 * 8 + warp_n] = s1;
            }
            __syncthreads();
            float S0 = 0.f, S1 = 0.f;
            #pragma unroll
            for (int w = 0; w < 8; w++) {
                S0 += redsum[row0 * 8 + w];
                S1 += redsum[row1 * 8 + w];
            }
            float inv0 = __frcp_rn(S0);
            float inv1 = __frcp_rn(S1);
            float* a0 = attn_s + row0 * N_ + warp_n * 64 + (lane & 3) * 2;
            float* a1 = attn_s + row1 * N_ + warp_n * 64 + (lane & 3) * 2;
            #pragma unroll
            for (int t = 0; t < 8; t++) {
                a0[t * 8]     += sc[t][0] * inv0;
                a0[t * 8 + 1] += sc[t][1] * inv0;
                a1[t * 8]     += sc[t][2] * inv1;
                a1[t * 8 + 1] += sc[t][3] * inv1;
            }
            __syncthreads();                        // red bufs reused next head
        }
    }

    for (int i = tid; i < 32 * N_; i += 512) {
        int r = i >> 9, m = i & (N_ - 1);
        attn[((size_t)b * N_ + n0 + r) * N_ + m] = attn_s[i];
    }
}

// ---------------- per-batch top-2 threshold + positions -------------------------
__global__ __launch_bounds__(256) void top2_kernel(
    const float* __restrict__ attn, int* __restrict__ pos, int* __restrict__ cnt)
{
    __shared__ float v1s[256], v2s[256];
    __shared__ float s_kth;
    __shared__ int   s_cnt;

    const int b = blockIdx.x;
    const int tid = threadIdx.x;
    const float* A = attn + (size_t)b * N_ * N_;

    float v1 = -FLT_MAX, v2 = -FLT_MAX;
    for (int i = tid; i < N_ * N_; i += 256) {
        float v = A[i];
        if (v > v1) { v2 = v1; v1 = v; }
        else if (v > v2) v2 = v;
    }
    v1s[tid] = v1; v2s[tid] = v2;
    __syncthreads();
    if (tid == 0) {
        float t1 = -FLT_MAX, t2 = -FLT_MAX;
        for (int i = 0; i < 256; i++) {
            float a = v1s[i], c = v2s[i];
            if (a > t1) { t2 = t1; t1 = a; } else if (a > t2) t2 = a;
            if (c > t1) { t2 = t1; t1 = c; } else if (c > t2) t2 = c;
        }
        s_kth = t2;
        s_cnt = 0;
    }
    __syncthreads();
    const float kth = s_kth;
    const int base = b * MAXP * 2;
    for (int i = tid; i < N_ * N_; i += 256) {
        if (A[i] >= kth) {
            int idx = atomicAdd(&s_cnt, 1);
            if (idx < MAXP) {
                pos[base + idx * 2]     = i >> 9;
                pos[base + idx * 2 + 1] = i & (N_ - 1);
            }
        }
    }
    __syncthreads();
    if (tid == 0) {
        int c = s_cnt < MAXP ? s_cnt : MAXP;
        for (int a2 = 1; a2 < c; a2++) {
            int ki = pos[base + a2 * 2], kj = pos[base + a2 * 2 + 1];
            int key = ki * N_ + kj;
            int p = a2 - 1;
            while (p >= 0) {
                int pi = pos[base + p * 2], pj = pos[base + p * 2 + 1];
                if (pi * N_ + pj <= key) break;
                pos[base + (p + 1) * 2] = pi;
                pos[base + (p + 1) * 2 + 1] = pj;
                p--;
            }
            pos[base + (p + 1) * 2] = ki;
            pos[base + (p + 1) * 2 + 1] = kj;
        }
        cnt[b] = c;
    }
}

// ---------------- sparse adjacency apply + GC epilogue --------------------------
__global__ __launch_bounds__(256) void out_kernel(
    const float* __restrict__ attn, const float* __restrict__ hidden,
    const float* __restrict__ bgc, const int* __restrict__ pos,
    const int* __restrict__ cnt, float* __restrict__ out)
{
    const int b = blockIdx.y;
    const int n = blockIdx.x;
    const int tid = threadIdx.x;

    __shared__ int   s_nc;
    __shared__ int   s_cols[2 * MAXP];
    __shared__ float s_w[2 * MAXP];
    __shared__ float s_wd, s_inv;

    if (tid == 0) {
        const float* An = attn + ((size_t)b * N_ + n) * N_;
        const int base = b * MAXP * 2;
        int c = cnt[b];
        int nc = 0;
        float wd = An[n];
        float sum = wd;
        for (int e = 0; e < c; e++) {
            int i = pos[base + e * 2], j = pos[base + e * 2 + 1];
            if (i == n && j != n) { float w = An[j]; s_cols[nc] = j; s_w[nc] = w; sum += w; nc++; }
            if (j == n && i != n) { float w = An[i]; s_cols[nc] = i; s_w[nc] = w; sum += w; nc++; }
        }
        s_nc = nc; s_wd = wd; s_inv = 1.f / (sum + 1.f);
    }
    __syncthreads();

    const int nc = s_nc;
    const float wd = s_wd, inv = s_inv;
    const float* hn = hidden + ((size_t)b * N_ + n) * D_;
    float* on = out + ((size_t)b * N_ + n) * D_;

    for (int d = tid; d < D_; d += 256) {
        float v = wd * hn[d];
        for (int e = 0; e < nc; e++)
            v += s_w[e] * hidden[((size_t)b * N_ + s_cols[e]) * D_ + d];
        v = v * inv + __ldg(&bgc[d]);
        on[d] = fmaxf(v, 0.f);
    }
}

// ---------------- launch ------------------------------------------------------
extern "C" void kernel_launch(void* const* d_in, const int* in_sizes, int n_in,
                              void* d_out, int out_size)
{
    const float* fuse = (const float*)d_in[0];
    const float* Wq   = (const float*)d_in[1];
    const float* bq   = (const float*)d_in[2];
    const float* Wk   = (const float*)d_in[3];
    const float* bk   = (const float*)d_in[4];
    const float* Wgc  = (const float*)d_in[5];
    const float* bgc  = (const float*)d_in[6];
    float* out = (float*)d_out;

    __half *Ahi, *Alo, *Bh, *Qhi, *Qlo, *Khi, *Klo;
    float *q, *k, *hid, *attn;
    int *pos, *cnt;
    cudaGetSymbolAddress((void**)&Ahi,  g_Ahi);
    cudaGetSymbolAddress((void**)&Alo,  g_Alo);
    cudaGetSymbolAddress((void**)&Bh,   g_Bh);
    cudaGetSymbolAddress((void**)&Qhi,  g_Qhi);
    cudaGetSymbolAddress((void**)&Qlo,  g_Qlo);
    cudaGetSymbolAddress((void**)&Khi,  g_Khi);
    cudaGetSymbolAddress((void**)&Klo,  g_Klo);
    cudaGetSymbolAddress((void**)&q,    g_q);
    cudaGetSymbolAddress((void**)&k,    g_k);
    cudaGetSymbolAddress((void**)&hid,  g_h);
    cudaGetSymbolAddress((void**)&attn, g_attn);
    cudaGetSymbolAddress((void**)&pos,  g_pos);
    cudaGetSymbolAddress((void**)&cnt,  g_cnt);

    // 0) fp16 hi/lo split of A (fuse) and fp16 fused-transposed B (Wq|Wk|Wgc)
    convA_kernel<<<(M_ * KP_ + 255) / 256, 256>>>(fuse, Ahi, Alo);
    convB_kernel<<<(NPAD_ * KP_ + 255) / 256, 256>>>(Wq, Wk, Wgc, Bh);

    // 1) fused HMMA GEMM -> q, k, hidden (fp32, contiguous epilogue)
    cudaFuncSetAttribute(gemm_hmma_kernel, cudaFuncAttributeMaxDynamicSharedMemorySize, GEMM_SMEM);
    gemm_hmma_kernel<<<dim3(NPAD_ / 128, M_ / 256), 256, GEMM_SMEM>>>(
        Ahi, Alo, Bh, bq, bk, q, k, hid);

    // 2) pack q/k head-padded fp16 hi/lo
    pack_qk_kernel<<<(BHN * 128 + 255) / 256, 256>>>(q, k, Qhi, Qlo, Khi, Klo);

    // 3) fused score GEMM + softmax + head-sum -> attn (512 threads / 16 warps)
    cudaFuncSetAttribute(attn_fused_kernel, cudaFuncAttributeMaxDynamicSharedMemorySize, AT_SMEM);
    attn_fused_kernel<<<dim3(N_ / 32, B_), 512, AT_SMEM>>>(Qhi, Qlo, Khi, Klo, attn);

    // 4) per-batch top-2 threshold + sparse positions
    top2_kernel<<<B_, 256>>>(attn, pos, cnt);

    // 5) sparse adjacency apply + graph-conv epilogue
    out_kernel<<<dim3(N_, B_), 256>>>(attn, hid, bgc, pos, cnt, out);
}

// round 8
// speedup vs baseline: 1.2541x; 1.2234x over previous
#include <cuda_runtime.h>
#include <cuda_fp16.h>
#include <cfloat>
#include <cstdint>

// Problem constants
#define B_   32
#define N_   512
#define D_   791
#define H_   7
#define DK_  113
#define M_   (B_ * N_)     // 16384
#define MAXP 64

// main HMMA GEMM geometry: CTA 256x128, warp tile 64x64, 8 warps, 4-stage cp.async
#define KP_     832          // padded K (13 * 64)
#define NCH     13           // single hi term, 13 chunks of K=64
#define NPAD_   2432         // fused N = 3*791 = 2373 padded to 19*128
#define STAGE_B 49152        // A 256x64 fp16 (32KB) + B 128x64 fp16 (16KB)
#define GEMM_SMEM (4 * STAGE_B + 256)
#define BHN (B_ * H_ * N_)   // 114688 packed rows

// score GEMM geometry: CTA 128x128, warp tile 32x64, K = 3 terms x 128 (6 chunks)
#define SKP   128
#define SNCH  6
#define SSTAGE_B 32768
#define SGEMM_SMEM (4 * SSTAGE_B + 256)

// ---------------- scratch (device globals; no allocation allowed) -------------
__device__ __align__(256) __half g_Ahi[M_ * KP_];
__device__ __align__(256) __half g_Bh [NPAD_ * KP_];
__device__ __align__(256) __half g_Qhi[(size_t)BHN * SKP];
__device__ __align__(256) __half g_Qlo[(size_t)BHN * SKP];
__device__ __align__(256) __half g_Khi[(size_t)BHN * SKP];
__device__ __align__(256) __half g_Klo[(size_t)BHN * SKP];
__device__ float g_S[(size_t)B_ * H_ * N_ * N_];
__device__ float g_q[M_ * D_];
__device__ float g_k[M_ * D_];
__device__ float g_h[M_ * D_];
__device__ float g_attn[B_ * N_ * N_];
__device__ int   g_pos[B_ * MAXP * 2];
__device__ int   g_cnt[B_];

// ---------------- PTX helpers --------------------------------------------------
__device__ __forceinline__ uint32_t smem_u32(const void* p) {
    uint32_t a;
    asm("{ .reg .u64 t; cvta.to.shared.u64 t, %1; cvt.u32.u64 %0, t; }" : "=r"(a) : "l"(p));
    return a;
}
__device__ __forceinline__ void ldm4(uint32_t& r0, uint32_t& r1, uint32_t& r2,
                                     uint32_t& r3, uint32_t a) {
    asm volatile("ldmatrix.sync.aligned.m8n8.x4.shared.b16 {%0,%1,%2,%3}, [%4];"
                 : "=r"(r0), "=r"(r1), "=r"(r2), "=r"(r3) : "r"(a));
}
__device__ __forceinline__ void mma16816(float* d, const uint32_t* a, const uint32_t* b) {
    asm volatile(
        "mma.sync.aligned.m16n8k16.row.col.f32.f16.f16.f32 "
        "{%0,%1,%2,%3}, {%4,%5,%6,%7}, {%8,%9}, {%0,%1,%2,%3};"
        : "+f"(d[0]), "+f"(d[1]), "+f"(d[2]), "+f"(d[3])
        : "r"(a[0]), "r"(a[1]), "r"(a[2]), "r"(a[3]), "r"(b[0]), "r"(b[1]));
}
__device__ __forceinline__ void cpa16(uint32_t dst, const void* src) {
    asm volatile("cp.async.cg.shared.global [%0], [%1], 16;" :: "r"(dst), "l"(src));
}

// ---------------- conversions ----------------------------------------------------
__global__ __launch_bounds__(256) void convA_kernel(
    const float* __restrict__ fuse, __half* __restrict__ Ahi)
{
    int idx = blockIdx.x * 256 + threadIdx.x;      // over M_*KP_
    if (idx >= M_ * KP_) return;
    int m = idx / KP_, k = idx - m * KP_;
    float x = (k < D_) ? fuse[(size_t)m * D_ + k] : 0.f;
    Ahi[idx] = __float2half_rn(x);
}

__global__ __launch_bounds__(256) void zeroB_kernel(__half* __restrict__ Bh)
{
    int idx = blockIdx.x * 256 + threadIdx.x;      // over NPAD_*KP_/8 (half2 x4)
    if (idx * 8 >= NPAD_ * KP_) return;
    *reinterpret_cast<uint4*>(Bh + idx * 8) = make_uint4(0, 0, 0, 0);
}

// Coalesced transpose: Bh[z*791 + n][k] = W_z[k][n], 32x32 smem tiles.
__global__ __launch_bounds__(256) void transB_kernel(
    const float* __restrict__ Wq, const float* __restrict__ Wk,
    const float* __restrict__ Wgc, __half* __restrict__ Bh)
{
    __shared__ __half tile[32][33];
    const int z = blockIdx.z;
    const float* W = (z == 0) ? Wq : (z == 1) ? Wk : Wgc;
    const int k0 = blockIdx.x * 32;                // 0..800 step 32 (26 tiles covers 832)
    const int n0 = blockIdx.y * 32;                // 0..767+ (25 tiles covers 791)
    const int tx = threadIdx.x & 31, ty = threadIdx.x >> 5;  // 8 rows per pass

    #pragma unroll
    for (int rr = 0; rr < 4; rr++) {
        int k = k0 + ty + rr * 8;
        int n = n0 + tx;
        float v = (k < D_ && n < D_) ? W[(size_t)k * D_ + n] : 0.f;
        tile[ty + rr * 8][tx] = __float2half_rn(v);
    }
    __syncthreads();
    #pragma unroll
    for (int rr = 0; rr < 4; rr++) {
        int n = n0 + ty + rr * 8;
        int k = k0 + tx;
        if (n < D_ && k < KP_)
            Bh[(size_t)(z * D_ + n) * KP_ + k] = tile[tx][ty + rr * 8];
    }
}

// ---------------- HMMA fused GEMM (single hi term) -------------------------------
__device__ __forceinline__ void issue_chunk(
    int cc, int tid, int m0, int nt0, uint32_t sb,
    const __half* __restrict__ Ahi, const __half* __restrict__ Bh)
{
    const int kk0 = cc * 64;
    const uint32_t st = sb + (cc & 3) * STAGE_B;
    #pragma unroll
    for (int it = 0; it < 8; it++) {               // A: 2048 x 16B
        int i = tid + it * 256;
        int r = i >> 3, u = i & 7;
        const __half* src = Ahi + (size_t)(m0 + r) * KP_ + kk0 + u * 8;
        cpa16(st + r * 128 + (((u ^ (r & 7))) << 4), src);
    }
    #pragma unroll
    for (int it = 0; it < 4; it++) {               // B: 1024 x 16B
        int i = tid + it * 256;
        int r = i >> 3, u = i & 7;
        const __half* src = Bh + (size_t)(nt0 + r) * KP_ + kk0 + u * 8;
        cpa16(st + 32768 + r * 128 + (((u ^ (r & 7))) << 4), src);
    }
    asm volatile("cp.async.commit_group;" ::: "memory");
}

__global__ __launch_bounds__(256, 1) void gemm_hmma_kernel(
    const __half* __restrict__ Ahi, const __half* __restrict__ Bh,
    const float* __restrict__ bq, const float* __restrict__ bk,
    float* __restrict__ q, float* __restrict__ kk, float* __restrict__ hid)
{
    extern __shared__ char smc[];
    const uint32_t sb = (smem_u32(smc) + 127) & ~127u;
    const int tid = threadIdx.x;
    const int wid = tid >> 5, lane = tid & 31;
    const int m0 = blockIdx.y * 256;
    const int nt0 = blockIdx.x * 128;

    float acc[4][8][4];
    #pragma unroll
    for (int t = 0; t < 4; t++)
        #pragma unroll
        for (int j = 0; j < 8; j++)
            #pragma unroll
            for (int e = 0; e < 4; e++) acc[t][j][e] = 0.f;

    issue_chunk(0, tid, m0, nt0, sb, Ahi, Bh);
    issue_chunk(1, tid, m0, nt0, sb, Ahi, Bh);
    issue_chunk(2, tid, m0, nt0, sb, Ahi, Bh);

    const int warp_m = wid & 3, warp_n = wid >> 2;
    const int rowinA = (lane & 7) + ((lane >> 3) & 1) * 8;
    const int hbA    = lane >> 4;
    const int rowinB = (lane & 7) + ((lane >> 4) & 1) * 8;
    const int hbB    = (lane >> 3) & 1;

    for (int cc = 0; cc < NCH; cc++) {
        const int rem = NCH - 1 - cc;
        if (rem >= 2)      asm volatile("cp.async.wait_group 2;" ::: "memory");
        else if (rem == 1) asm volatile("cp.async.wait_group 1;" ::: "memory");
        else               asm volatile("cp.async.wait_group 0;" ::: "memory");
        __syncthreads();
        if (cc + 3 < NCH) issue_chunk(cc + 3, tid, m0, nt0, sb, Ahi, Bh);

        const uint32_t st = sb + (cc & 3) * STAGE_B;
        #pragma unroll
        for (int s = 0; s < 4; s++) {
            uint32_t a[4][4], b[8][2];
            #pragma unroll
            for (int t = 0; t < 4; t++) {
                int r = warp_m * 64 + t * 16 + rowinA;
                uint32_t ad = st + r * 128 + ((((s << 1) | hbA) ^ (r & 7)) << 4);
                ldm4(a[t][0], a[t][1], a[t][2], a[t][3], ad);
            }
            #pragma unroll
            for (int jj = 0; jj < 4; jj++) {
                int r = warp_n * 64 + jj * 16 + rowinB;
                uint32_t ad = st + 32768 + r * 128 + ((((s << 1) | hbB) ^ (r & 7)) << 4);
                ldm4(b[2 * jj][0], b[2 * jj][1], b[2 * jj + 1][0], b[2 * jj + 1][1], ad);
            }
            #pragma unroll
            for (int t = 0; t < 4; t++)
                #pragma unroll
                for (int j = 0; j < 8; j++)
                    mma16816(acc[t][j], a[t], b[j]);
        }
    }

    // epilogue: demux to q | k | hid with bias (contiguous fp32 stores)
    #pragma unroll
    for (int t = 0; t < 4; t++) {
        const int row0 = m0 + warp_m * 64 + t * 16 + (lane >> 2);
        #pragma unroll
        for (int j = 0; j < 8; j++) {
            const int col = nt0 + warp_n * 64 + j * 8 + (lane & 3) * 2;
            #pragma unroll
            for (int half = 0; half < 2; half++) {
                const int row = row0 + half * 8;
                const float v0 = acc[t][j][half * 2];
                const float v1 = acc[t][j][half * 2 + 1];
                #pragma unroll
                for (int e = 0; e < 2; e++) {
                    const int c = col + e;
                    const float v = e ? v1 : v0;
                    if (c < D_)
                        q[(size_t)row * D_ + c] = v + __ldg(&bq[c]);
                    else if (c < 2 * D_)
                        kk[(size_t)row * D_ + (c - D_)] = v + __ldg(&bk[c - D_]);
                    else if (c < 3 * D_)
                        hid[(size_t)row * D_ + (c - 2 * D_)] = v;
                }
            }
        }
    }
}

// ---------------- pack q/k into head-padded fp16 hi/lo --------------------------
__global__ __launch_bounds__(256) void pack_qk_kernel(
    const float* __restrict__ q, const float* __restrict__ k,
    __half* __restrict__ Qhi, __half* __restrict__ Qlo,
    __half* __restrict__ Khi, __half* __restrict__ Klo)
{
    int idx = blockIdx.x * 256 + threadIdx.x;      // over BHN*128
    if (idx >= BHN * SKP) return;
    int dk = idx & 127;
    int rest = idx >> 7;
    int n = rest & (N_ - 1);
    int bh = rest >> 9;
    int h = bh % H_, b = bh / H_;
    float qv = 0.f, kv = 0.f;
    if (dk < DK_) {
        size_t off = ((size_t)(b * N_ + n)) * D_ + h * DK_ + dk;
        qv = q[off];
        kv = k[off];
    }
    __half qh = __float2half_rn(qv);
    __half kh = __float2half_rn(kv);
    Qhi[idx] = qh;
    Qlo[idx] = __float2half_rn(qv - __half2float(qh));
    Khi[idx] = kh;
    Klo[idx] = __float2half_rn(kv - __half2float(kh));
}

// ---------------- HMMA score GEMM ------------------------------------------------
// S[bh] = (Qhi+Qlo)@Khi^T + Qhi@Klo^T, scaled by 1/sqrt(113).
__device__ __forceinline__ void issue_chunk_s(
    int cc, int tid, int m0, int nt0, int bh, uint32_t sb,
    const __half* __restrict__ Qhi, const __half* __restrict__ Qlo,
    const __half* __restrict__ Khi, const __half* __restrict__ Klo)
{
    const int p = cc >> 1;
    const int kk0 = (cc & 1) * 64;
    const __half* As = (p == 1) ? Qlo : Qhi;
    const __half* Bs = (p == 2) ? Klo : Khi;
    const size_t base = (size_t)bh * N_ * SKP;
    const uint32_t st = sb + (cc & 3) * SSTAGE_B;
    #pragma unroll
    for (int it = 0; it < 4; it++) {               // A: 1024 x 16B
        int i = tid + it * 256;
        int r = i >> 3, u = i & 7;
        const __half* src = As + base + (size_t)(m0 + r) * SKP + kk0 + u * 8;
        cpa16(st + r * 128 + (((u ^ (r & 7))) << 4), src);
    }
    #pragma unroll
    for (int it = 0; it < 4; it++) {               // B: 1024 x 16B
        int i = tid + it * 256;
        int r = i >> 3, u = i & 7;
        const __half* src = Bs + base + (size_t)(nt0 + r) * SKP + kk0 + u * 8;
        cpa16(st + 16384 + r * 128 + (((u ^ (r & 7))) << 4), src);
    }
    asm volatile("cp.async.commit_group;" ::: "memory");
}

__global__ __launch_bounds__(256, 1) void score_hmma_kernel(
    const __half* __restrict__ Qhi, const __half* __restrict__ Qlo,
    const __half* __restrict__ Khi, const __half* __restrict__ Klo,
    float* __restrict__ S)
{
    extern __shared__ char smc[];
    const uint32_t sb = (smem_u32(smc) + 127) & ~127u;
    const int tid = threadIdx.x;
    const int wid = tid >> 5, lane = tid & 31;
    const int m0 = blockIdx.y * 128;
    const int nt0 = blockIdx.x * 128;
    const int bh = blockIdx.z;

    float acc[2][8][4];
    #pragma unroll
    for (int t = 0; t < 2; t++)
        #pragma unroll
        for (int j = 0; j < 8; j++)
            #pragma unroll
            for (int e = 0; e < 4; e++) acc[t][j][e] = 0.f;

    issue_chunk_s(0, tid, m0, nt0, bh, sb, Qhi, Qlo, Khi, Klo);
    issue_chunk_s(1, tid, m0, nt0, bh, sb, Qhi, Qlo, Khi, Klo);
    issue_chunk_s(2, tid, m0, nt0, bh, sb, Qhi, Qlo, Khi, Klo);

    const int warp_m = wid & 3, warp_n = wid >> 2;
    const int rowinA = (lane & 7) + ((lane >> 3) & 1) * 8;
    const int hbA    = lane >> 4;
    const int rowinB = (lane & 7) + ((lane >> 4) & 1) * 8;
    const int hbB    = (lane >> 3) & 1;

    for (int cc = 0; cc < SNCH; cc++) {
        const int rem = SNCH - 1 - cc;
        if (rem >= 2)      asm volatile("cp.async.wait_group 2;" ::: "memory");
        else if (rem == 1) asm volatile("cp.async.wait_group 1;" ::: "memory");
        else               asm volatile("cp.async.wait_group 0;" ::: "memory");
        __syncthreads();
        if (cc + 3 < SNCH) issue_chunk_s(cc + 3, tid, m0, nt0, bh, sb, Qhi, Qlo, Khi, Klo);

        const uint32_t st = sb + (cc & 3) * SSTAGE_B;
        #pragma unroll
        for (int s = 0; s < 4; s++) {
            uint32_t a[2][4], b[8][2];
            #pragma unroll
            for (int t = 0; t < 2; t++) {
                int r = warp_m * 32 + t * 16 + rowinA;
                uint32_t ad = st + r * 128 + ((((s << 1) | hbA) ^ (r & 7)) << 4);
                ldm4(a[t][0], a[t][1], a[t][2], a[t][3], ad);
            }
            #pragma unroll
            for (int jj = 0; jj < 4; jj++) {
                int r = warp_n * 64 + jj * 16 + rowinB;
                uint32_t ad = st + 16384 + r * 128 + ((((s << 1) | hbB) ^ (r & 7)) << 4);
                ldm4(b[2 * jj][0], b[2 * jj][1], b[2 * jj + 1][0], b[2 * jj + 1][1], ad);
            }
            #pragma unroll
            for (int t = 0; t < 2; t++)
                #pragma unroll
                for (int j = 0; j < 8; j++)
                    mma16816(acc[t][j], a[t], b[j]);
        }
    }

    const float scale = rsqrtf((float)DK_);
    float* Sb = S + (size_t)bh * N_ * N_;
    #pragma unroll
    for (int t = 0; t < 2; t++) {
        const int row0 = m0 + warp_m * 32 + t * 16 + (lane >> 2);
        #pragma unroll
        for (int j = 0; j < 8; j++) {
            const int col = nt0 + warp_n * 64 + j * 8 + (lane & 3) * 2;
            #pragma unroll
            for (int half = 0; half < 2; half++) {
                const int row = row0 + half * 8;
                Sb[(size_t)row * N_ + col]     = acc[t][j][half * 2] * scale;
                Sb[(size_t)row * N_ + col + 1] = acc[t][j][half * 2 + 1] * scale;
            }
        }
    }
}

// ---------------- softmax + head-sum -> attn -------------------------------------
__global__ __launch_bounds__(256) void softmax_kernel(
    const float* __restrict__ S, float* __restrict__ attn)
{
    __shared__ float e[H_][N_];
    __shared__ float winv[H_];

    const int tid = threadIdx.x;
    const int wid = tid >> 5, lane = tid & 31;
    const int ng = blockIdx.x;                 // global row 0..16383
    const int b = ng >> 9, n = ng & (N_ - 1);

    if (wid < H_) {
        const float* Sr = S + ((size_t)(b * H_ + wid) * N_ + n) * N_;
        float mx = -FLT_MAX;
        float v[16];
        #pragma unroll
        for (int it = 0; it < 16; it++) {
            v[it] = Sr[lane + it * 32];
            mx = fmaxf(mx, v[it]);
        }
        #pragma unroll
        for (int o = 16; o > 0; o >>= 1) mx = fmaxf(mx, __shfl_xor_sync(0xFFFFFFFFu, mx, o));
        float sum = 0.f;
        #pragma unroll
        for (int it = 0; it < 16; it++) {
            float ex = __expf(v[it] - mx);
            e[wid][lane + it * 32] = ex;
            sum += ex;
        }
        #pragma unroll
        for (int o = 16; o > 0; o >>= 1) sum += __shfl_xor_sync(0xFFFFFFFFu, sum, o);
        if (lane == 0) winv[wid] = __frcp_rn(sum);
    }
    __syncthreads();

    float* an = attn + (size_t)ng * N_;
    for (int m = tid; m < N_; m += 256) {
        float a = 0.f;
        #pragma unroll
        for (int h = 0; h < H_; h++) a += e[h][m] * winv[h];
        an[m] = a;
    }
}

// ---------------- per-batch top-2 threshold + positions -------------------------
__global__ __launch_bounds__(256) void top2_kernel(
    const float* __restrict__ attn, int* __restrict__ pos, int* __restrict__ cnt)
{
    __shared__ float v1s[256], v2s[256];
    __shared__ float s_kth;
    __shared__ int   s_cnt;

    const int b = blockIdx.x;
    const int tid = threadIdx.x;
    const float* A = attn + (size_t)b * N_ * N_;

    float v1 = -FLT_MAX, v2 = -FLT_MAX;
    for (int i = tid; i < N_ * N_; i += 256) {
        float v = A[i];
        if (v > v1) { v2 = v1; v1 = v; }
        else if (v > v2) v2 = v;
    }
    v1s[tid] = v1; v2s[tid] = v2;
    __syncthreads();
    if (tid == 0) {
        float t1 = -FLT_MAX, t2 = -FLT_MAX;
        for (int i = 0; i < 256; i++) {
            float a = v1s[i], c = v2s[i];
            if (a > t1) { t2 = t1; t1 = a; } else if (a > t2) t2 = a;
            if (c > t1) { t2 = t1; t1 = c; } else if (c > t2) t2 = c;
        }
        s_kth = t2;
        s_cnt = 0;
    }
    __syncthreads();
    const float kth = s_kth;
    const int base = b * MAXP * 2;
    for (int i = tid; i < N_ * N_; i += 256) {
        if (A[i] >= kth) {
            int idx = atomicAdd(&s_cnt, 1);
            if (idx < MAXP) {
                pos[base + idx * 2]     = i >> 9;
                pos[base + idx * 2 + 1] = i & (N_ - 1);
            }
        }
    }
    __syncthreads();
    if (tid == 0) {
        int c = s_cnt < MAXP ? s_cnt : MAXP;
        for (int a2 = 1; a2 < c; a2++) {
            int ki = pos[base + a2 * 2], kj = pos[base + a2 * 2 + 1];
            int key = ki * N_ + kj;
            int p = a2 - 1;
            while (p >= 0) {
                int pi = pos[base + p * 2], pj = pos[base + p * 2 + 1];
                if (pi * N_ + pj <= key) break;
                pos[base + (p + 1) * 2] = pi;
                pos[base + (p + 1) * 2 + 1] = pj;
                p--;
            }
            pos[base + (p + 1) * 2] = ki;
            pos[base + (p + 1) * 2 + 1] = kj;
        }
        cnt[b] = c;
    }
}

// ---------------- sparse adjacency apply + GC epilogue --------------------------
__global__ __launch_bounds__(256) void out_kernel(
    const float* __restrict__ attn, const float* __restrict__ hidden,
    const float* __restrict__ bgc, const int* __restrict__ pos,
    const int* __restrict__ cnt, float* __restrict__ out)
{
    const int b = blockIdx.y;
    const int n = blockIdx.x;
    const int tid = threadIdx.x;

    __shared__ int   s_nc;
    __shared__ int   s_cols[2 * MAXP];
    __shared__ float s_w[2 * MAXP];
    __shared__ float s_wd, s_inv;

    if (tid == 0) {
        const float* An = attn + ((size_t)b * N_ + n) * N_;
        const int base = b * MAXP * 2;
        int c = cnt[b];
        int nc = 0;
        float wd = An[n];
        float sum = wd;
        for (int e = 0; e < c; e++) {
            int i = pos[base + e * 2], j = pos[base + e * 2 + 1];
            if (i == n && j != n) { float w = An[j]; s_cols[nc] = j; s_w[nc] = w; sum += w; nc++; }
            if (j == n && i != n) { float w = An[i]; s_cols[nc] = i; s_w[nc] = w; sum += w; nc++; }
        }
        s_nc = nc; s_wd = wd; s_inv = 1.f / (sum + 1.f);
    }
    __syncthreads();

    const int nc = s_nc;
    const float wd = s_wd, inv = s_inv;
    const float* hn = hidden + ((size_t)b * N_ + n) * D_;
    float* on = out + ((size_t)b * N_ + n) * D_;

    for (int d = tid; d < D_; d += 256) {
        float v = wd * hn[d];
        for (int e = 0; e < nc; e++)
            v += s_w[e] * hidden[((size_t)b * N_ + s_cols[e]) * D_ + d];
        v = v * inv + __ldg(&bgc[d]);
        on[d] = fmaxf(v, 0.f);
    }
}

// ---------------- launch ------------------------------------------------------
extern "C" void kernel_launch(void* const* d_in, const int* in_sizes, int n_in,
                              void* d_out, int out_size)
{
    const float* fuse = (const float*)d_in[0];
    const float* Wq   = (const float*)d_in[1];
    const float* bq   = (const float*)d_in[2];
    const float* Wk   = (const float*)d_in[3];
    const float* bk   = (const float*)d_in[4];
    const float* Wgc  = (const float*)d_in[5];
    const float* bgc  = (const float*)d_in[6];
    float* out = (float*)d_out;

    __half *Ahi, *Bh, *Qhi, *Qlo, *Khi, *Klo;
    float *q, *k, *hid, *attn, *S;
    int *pos, *cnt;
    cudaGetSymbolAddress((void**)&Ahi,  g_Ahi);
    cudaGetSymbolAddress((void**)&Bh,   g_Bh);
    cudaGetSymbolAddress((void**)&Qhi,  g_Qhi);
    cudaGetSymbolAddress((void**)&Qlo,  g_Qlo);
    cudaGetSymbolAddress((void**)&Khi,  g_Khi);
    cudaGetSymbolAddress((void**)&Klo,  g_Klo);
    cudaGetSymbolAddress((void**)&S,    g_S);
    cudaGetSymbolAddress((void**)&q,    g_q);
    cudaGetSymbolAddress((void**)&k,    g_k);
    cudaGetSymbolAddress((void**)&hid,  g_h);
    cudaGetSymbolAddress((void**)&attn, g_attn);
    cudaGetSymbolAddress((void**)&pos,  g_pos);
    cudaGetSymbolAddress((void**)&cnt,  g_cnt);

    // 0) fp16 conversions: A hi-only; B via zero-fill + coalesced transpose
    convA_kernel<<<(M_ * KP_ + 255) / 256, 256>>>(fuse, Ahi);
    zeroB_kernel<<<(NPAD_ * KP_ / 8 + 255) / 256, 256>>>(Bh);
    transB_kernel<<<dim3(KP_ / 32, (D_ + 31) / 32, 3), 256>>>(Wq, Wk, Wgc, Bh);

    // 1) fused HMMA GEMM (hi term only) -> q, k, hidden
    cudaFuncSetAttribute(gemm_hmma_kernel, cudaFuncAttributeMaxDynamicSharedMemorySize, GEMM_SMEM);
    gemm_hmma_kernel<<<dim3(NPAD_ / 128, M_ / 256), 256, GEMM_SMEM>>>(
        Ahi, Bh, bq, bk, q, k, hid);

    // 2) pack q/k head-padded fp16 hi/lo
    pack_qk_kernel<<<(BHN * SKP + 255) / 256, 256>>>(q, k, Qhi, Qlo, Khi, Klo);

    // 3) HMMA score GEMM -> S[B,H,N,N]
    cudaFuncSetAttribute(score_hmma_kernel, cudaFuncAttributeMaxDynamicSharedMemorySize, SGEMM_SMEM);
    score_hmma_kernel<<<dim3(N_ / 128, N_ / 128, B_ * H_), 256, SGEMM_SMEM>>>(
        Qhi, Qlo, Khi, Klo, S);

    // 4) softmax + head-sum -> attn
    softmax_kernel<<<M_, 256>>>(S, attn);

    // 5) per-batch top-2 threshold + sparse positions
    top2_kernel<<<B_, 256>>>(attn, pos, cnt);

    // 6) sparse adjacency apply + graph-conv epilogue
    out_kernel<<<dim3(N_, B_), 256>>>(attn, hid, bgc, pos, cnt, out);
}

// round 9
// speedup vs baseline: 1.5253x; 1.2163x over previous
#include <cuda_runtime.h>
#include <cuda_fp16.h>
#include <cfloat>
#include <cstdint>

// Problem constants
#define B_   32
#define N_   512
#define D_   791
#define H_   7
#define DK_  113
#define M_   (B_ * N_)     // 16384
#define MAXP 64

// main HMMA GEMM: CTA 128x128, warp tile 32x64, 8 warps, 3-stage, 2 CTA/SM
#define KP_     832          // padded K (13 * 64)
#define NCH     13           // single hi term, 13 chunks of K=64
#define NPAD_   2432         // fused N = 3*791 = 2373 padded to 19*128
#define STAGE_B 32768        // A 128x64 fp16 (16KB) + B 128x64 fp16 (16KB)
#define GEMM_SMEM (3 * STAGE_B + 256)
#define BHN (B_ * H_ * N_)   // 114688 packed rows

// score GEMM: CTA 128x128, warp tile 32x64, K = 3 terms x 128 (6 chunks), 3-stage
#define SKP   128
#define SNCH  6
#define SSTAGE_B 32768
#define SGEMM_SMEM (3 * SSTAGE_B + 256)

// ---------------- scratch (device globals; no allocation allowed) -------------
__device__ __align__(256) __half g_Ahi[M_ * KP_];
__device__ __align__(256) __half g_Bh [NPAD_ * KP_];
__device__ __align__(256) __half g_Qhi[(size_t)BHN * SKP];
__device__ __align__(256) __half g_Qlo[(size_t)BHN * SKP];
__device__ __align__(256) __half g_Khi[(size_t)BHN * SKP];
__device__ __align__(256) __half g_Klo[(size_t)BHN * SKP];
__device__ float g_S[(size_t)B_ * H_ * N_ * N_];
__device__ float g_q[M_ * D_];
__device__ float g_k[M_ * D_];
__device__ float g_h[M_ * D_];
__device__ float g_attn[B_ * N_ * N_];
__device__ int   g_pos[B_ * MAXP * 2];
__device__ int   g_cnt[B_];

// ---------------- PTX helpers --------------------------------------------------
__device__ __forceinline__ uint32_t smem_u32(const void* p) {
    uint32_t a;
    asm("{ .reg .u64 t; cvta.to.shared.u64 t, %1; cvt.u32.u64 %0, t; }" : "=r"(a) : "l"(p));
    return a;
}
__device__ __forceinline__ void ldm4(uint32_t& r0, uint32_t& r1, uint32_t& r2,
                                     uint32_t& r3, uint32_t a) {
    asm volatile("ldmatrix.sync.aligned.m8n8.x4.shared.b16 {%0,%1,%2,%3}, [%4];"
                 : "=r"(r0), "=r"(r1), "=r"(r2), "=r"(r3) : "r"(a));
}
__device__ __forceinline__ void mma16816(float* d, const uint32_t* a, const uint32_t* b) {
    asm volatile(
        "mma.sync.aligned.m16n8k16.row.col.f32.f16.f16.f32 "
        "{%0,%1,%2,%3}, {%4,%5,%6,%7}, {%8,%9}, {%0,%1,%2,%3};"
        : "+f"(d[0]), "+f"(d[1]), "+f"(d[2]), "+f"(d[3])
        : "r"(a[0]), "r"(a[1]), "r"(a[2]), "r"(a[3]), "r"(b[0]), "r"(b[1]));
}
__device__ __forceinline__ void cpa16(uint32_t dst, const void* src) {
    asm volatile("cp.async.cg.shared.global [%0], [%1], 16;" :: "r"(dst), "l"(src));
}

// ---------------- conversions ----------------------------------------------------
// 4 elems/thread, vector store (uint2 = 4 halves)
__global__ __launch_bounds__(256) void convA_kernel(
    const float* __restrict__ fuse, __half* __restrict__ Ahi)
{
    int idx = blockIdx.x * 256 + threadIdx.x;      // over M_*KP_/4
    if (idx >= M_ * KP_ / 4) return;
    int m = idx / (KP_ / 4);
    int k = (idx - m * (KP_ / 4)) * 4;
    const float* src = fuse + (size_t)m * D_ + k;
    float x0 = (k     < D_) ? __ldg(src)     : 0.f;
    float x1 = (k + 1 < D_) ? __ldg(src + 1) : 0.f;
    float x2 = (k + 2 < D_) ? __ldg(src + 2) : 0.f;
    float x3 = (k + 3 < D_) ? __ldg(src + 3) : 0.f;
    __half2 h01 = __floats2half2_rn(x0, x1);
    __half2 h23 = __floats2half2_rn(x2, x3);
    uint2 o;
    o.x = *reinterpret_cast<uint32_t*>(&h01);
    o.y = *reinterpret_cast<uint32_t*>(&h23);
    *reinterpret_cast<uint2*>(Ahi + (size_t)idx * 4) = o;
}

__global__ __launch_bounds__(256) void zeroB_kernel(__half* __restrict__ Bh)
{
    int idx = blockIdx.x * 256 + threadIdx.x;      // over NPAD_*KP_/8
    if (idx * 8 >= NPAD_ * KP_) return;
    *reinterpret_cast<uint4*>(Bh + idx * 8) = make_uint4(0, 0, 0, 0);
}

// Coalesced transpose: Bh[z*791 + n][k] = W_z[k][n], 32x32 smem tiles.
__global__ __launch_bounds__(256) void transB_kernel(
    const float* __restrict__ Wq, const float* __restrict__ Wk,
    const float* __restrict__ Wgc, __half* __restrict__ Bh)
{
    __shared__ __half tile[32][33];
    const int z = blockIdx.z;
    const float* W = (z == 0) ? Wq : (z == 1) ? Wk : Wgc;
    const int k0 = blockIdx.x * 32;
    const int n0 = blockIdx.y * 32;
    const int tx = threadIdx.x & 31, ty = threadIdx.x >> 5;

    #pragma unroll
    for (int rr = 0; rr < 4; rr++) {
        int k = k0 + ty + rr * 8;
        int n = n0 + tx;
        float v = (k < D_ && n < D_) ? W[(size_t)k * D_ + n] : 0.f;
        tile[ty + rr * 8][tx] = __float2half_rn(v);
    }
    __syncthreads();
    #pragma unroll
    for (int rr = 0; rr < 4; rr++) {
        int n = n0 + ty + rr * 8;
        int k = k0 + tx;
        if (n < D_ && k < KP_)
            Bh[(size_t)(z * D_ + n) * KP_ + k] = tile[tx][ty + rr * 8];
    }
}

// ---------------- HMMA fused GEMM (single hi term, 128x128, 3-stage) -------------
__device__ __forceinline__ void issue_chunk(
    int cc, int tid, int m0, int nt0, uint32_t sb,
    const __half* __restrict__ Ahi, const __half* __restrict__ Bh)
{
    const int kk0 = cc * 64;
    const uint32_t st = sb + (cc % 3) * STAGE_B;
    #pragma unroll
    for (int it = 0; it < 4; it++) {               // A: 1024 x 16B
        int i = tid + it * 256;
        int r = i >> 3, u = i & 7;
        const __half* src = Ahi + (size_t)(m0 + r) * KP_ + kk0 + u * 8;
        cpa16(st + r * 128 + (((u ^ (r & 7))) << 4), src);
    }
    #pragma unroll
    for (int it = 0; it < 4; it++) {               // B: 1024 x 16B
        int i = tid + it * 256;
        int r = i >> 3, u = i & 7;
        const __half* src = Bh + (size_t)(nt0 + r) * KP_ + kk0 + u * 8;
        cpa16(st + 16384 + r * 128 + (((u ^ (r & 7))) << 4), src);
    }
    asm volatile("cp.async.commit_group;" ::: "memory");
}

__global__ __launch_bounds__(256, 2) void gemm_hmma_kernel(
    const __half* __restrict__ Ahi, const __half* __restrict__ Bh,
    const float* __restrict__ bq, const float* __restrict__ bk,
    float* __restrict__ q, float* __restrict__ kk, float* __restrict__ hid)
{
    extern __shared__ char smc[];
    const uint32_t sb = (smem_u32(smc) + 127) & ~127u;
    const int tid = threadIdx.x;
    const int wid = tid >> 5, lane = tid & 31;
    const int m0 = blockIdx.y * 128;
    const int nt0 = blockIdx.x * 128;

    float acc[2][8][4];
    #pragma unroll
    for (int t = 0; t < 2; t++)
        #pragma unroll
        for (int j = 0; j < 8; j++)
            #pragma unroll
            for (int e = 0; e < 4; e++) acc[t][j][e] = 0.f;

    issue_chunk(0, tid, m0, nt0, sb, Ahi, Bh);
    issue_chunk(1, tid, m0, nt0, sb, Ahi, Bh);

    const int warp_m = wid & 3, warp_n = wid >> 2;
    const int rowinA = (lane & 7) + ((lane >> 3) & 1) * 8;
    const int hbA    = lane >> 4;
    const int rowinB = (lane & 7) + ((lane >> 4) & 1) * 8;
    const int hbB    = (lane >> 3) & 1;

    for (int cc = 0; cc < NCH; cc++) {
        if (cc == NCH - 1) asm volatile("cp.async.wait_group 0;" ::: "memory");
        else               asm volatile("cp.async.wait_group 1;" ::: "memory");
        __syncthreads();
        if (cc + 2 < NCH) issue_chunk(cc + 2, tid, m0, nt0, sb, Ahi, Bh);

        const uint32_t st = sb + (cc % 3) * STAGE_B;
        #pragma unroll
        for (int s = 0; s < 4; s++) {
            uint32_t a[2][4], b[8][2];
            #pragma unroll
            for (int t = 0; t < 2; t++) {
                int r = warp_m * 32 + t * 16 + rowinA;
                uint32_t ad = st + r * 128 + ((((s << 1) | hbA) ^ (r & 7)) << 4);
                ldm4(a[t][0], a[t][1], a[t][2], a[t][3], ad);
            }
            #pragma unroll
            for (int jj = 0; jj < 4; jj++) {
                int r = warp_n * 64 + jj * 16 + rowinB;
                uint32_t ad = st + 16384 + r * 128 + ((((s << 1) | hbB) ^ (r & 7)) << 4);
                ldm4(b[2 * jj][0], b[2 * jj][1], b[2 * jj + 1][0], b[2 * jj + 1][1], ad);
            }
            #pragma unroll
            for (int t = 0; t < 2; t++)
                #pragma unroll
                for (int j = 0; j < 8; j++)
                    mma16816(acc[t][j], a[t], b[j]);
        }
    }

    // epilogue: demux to q | k | hid with bias (contiguous fp32 stores)
    #pragma unroll
    for (int t = 0; t < 2; t++) {
        const int row0 = m0 + warp_m * 32 + t * 16 + (lane >> 2);
        #pragma unroll
        for (int j = 0; j < 8; j++) {
            const int col = nt0 + warp_n * 64 + j * 8 + (lane & 3) * 2;
            #pragma unroll
            for (int half = 0; half < 2; half++) {
                const int row = row0 + half * 8;
                const float v0 = acc[t][j][half * 2];
                const float v1 = acc[t][j][half * 2 + 1];
                #pragma unroll
                for (int e = 0; e < 2; e++) {
                    const int c = col + e;
                    const float v = e ? v1 : v0;
                    if (c < D_)
                        q[(size_t)row * D_ + c] = v + __ldg(&bq[c]);
                    else if (c < 2 * D_)
                        kk[(size_t)row * D_ + (c - D_)] = v + __ldg(&bk[c - D_]);
                    else if (c < 3 * D_)
                        hid[(size_t)row * D_ + (c - 2 * D_)] = v;
                }
            }
        }
    }
}

// ---------------- pack q/k into head-padded fp16 hi/lo (8 elems/thread) ---------
__global__ __launch_bounds__(256) void pack_qk_kernel(
    const float* __restrict__ q, const float* __restrict__ k,
    __half* __restrict__ Qhi, __half* __restrict__ Qlo,
    __half* __restrict__ Khi, __half* __restrict__ Klo)
{
    int idx = blockIdx.x * 256 + threadIdx.x;      // over BHN*16 (8 elems each)
    if (idx >= BHN * 16) return;
    const int dk0 = (idx & 15) * 8;
    const int rest = idx >> 4;
    const int n = rest & (N_ - 1);
    const int bh = rest >> 9;
    const int h = bh % H_, b = bh / H_;
    const size_t off = ((size_t)(b * N_ + n)) * D_ + h * DK_;

    uint32_t qh[4], ql[4], kh[4], kl[4];
    #pragma unroll
    for (int p = 0; p < 4; p++) {
        float qv0 = 0.f, qv1 = 0.f, kv0 = 0.f, kv1 = 0.f;
        int d0 = dk0 + p * 2, d1 = d0 + 1;
        if (d0 < DK_) { qv0 = __ldg(&q[off + d0]); kv0 = __ldg(&k[off + d0]); }
        if (d1 < DK_) { qv1 = __ldg(&q[off + d1]); kv1 = __ldg(&k[off + d1]); }
        __half2 qh2 = __floats2half2_rn(qv0, qv1);
        __half2 kh2 = __floats2half2_rn(kv0, kv1);
        __half2 ql2 = __floats2half2_rn(qv0 - __half2float(__low2half(qh2)),
                                        qv1 - __half2float(__high2half(qh2)));
        __half2 kl2 = __floats2half2_rn(kv0 - __half2float(__low2half(kh2)),
                                        kv1 - __half2float(__high2half(kh2)));
        qh[p] = *reinterpret_cast<uint32_t*>(&qh2);
        ql[p] = *reinterpret_cast<uint32_t*>(&ql2);
        kh[p] = *reinterpret_cast<uint32_t*>(&kh2);
        kl[p] = *reinterpret_cast<uint32_t*>(&kl2);
    }
    const size_t dst = (size_t)idx * 8;
    *reinterpret_cast<uint4*>(Qhi + dst) = make_uint4(qh[0], qh[1], qh[2], qh[3]);
    *reinterpret_cast<uint4*>(Qlo + dst) = make_uint4(ql[0], ql[1], ql[2], ql[3]);
    *reinterpret_cast<uint4*>(Khi + dst) = make_uint4(kh[0], kh[1], kh[2], kh[3]);
    *reinterpret_cast<uint4*>(Klo + dst) = make_uint4(kl[0], kl[1], kl[2], kl[3]);
}

// ---------------- HMMA score GEMM (3-stage, 2 CTA/SM) ----------------------------
__device__ __forceinline__ void issue_chunk_s(
    int cc, int tid, int m0, int nt0, int bh, uint32_t sb,
    const __half* __restrict__ Qhi, const __half* __restrict__ Qlo,
    const __half* __restrict__ Khi, const __half* __restrict__ Klo)
{
    const int p = cc >> 1;
    const int kk0 = (cc & 1) * 64;
    const __half* As = (p == 1) ? Qlo : Qhi;
    const __half* Bs = (p == 2) ? Klo : Khi;
    const size_t base = (size_t)bh * N_ * SKP;
    const uint32_t st = sb + (cc % 3) * SSTAGE_B;
    #pragma unroll
    for (int it = 0; it < 4; it++) {               // A: 1024 x 16B
        int i = tid + it * 256;
        int r = i >> 3, u = i & 7;
        const __half* src = As + base + (size_t)(m0 + r) * SKP + kk0 + u * 8;
        cpa16(st + r * 128 + (((u ^ (r & 7))) << 4), src);
    }
    #pragma unroll
    for (int it = 0; it < 4; it++) {               // B: 1024 x 16B
        int i = tid + it * 256;
        int r = i >> 3, u = i & 7;
        const __half* src = Bs + base + (size_t)(nt0 + r) * SKP + kk0 + u * 8;
        cpa16(st + 16384 + r * 128 + (((u ^ (r & 7))) << 4), src);
    }
    asm volatile("cp.async.commit_group;" ::: "memory");
}

__global__ __launch_bounds__(256, 2) void score_hmma_kernel(
    const __half* __restrict__ Qhi, const __half* __restrict__ Qlo,
    const __half* __restrict__ Khi, const __half* __restrict__ Klo,
    float* __restrict__ S)
{
    extern __shared__ char smc[];
    const uint32_t sb = (smem_u32(smc) + 127) & ~127u;
    const int tid = threadIdx.x;
    const int wid = tid >> 5, lane = tid & 31;
    const int m0 = blockIdx.y * 128;
    const int nt0 = blockIdx.x * 128;
    const int bh = blockIdx.z;

    float acc[2][8][4];
    #pragma unroll
    for (int t = 0; t < 2; t++)
        #pragma unroll
        for (int j = 0; j < 8; j++)
            #pragma unroll
            for (int e = 0; e < 4; e++) acc[t][j][e] = 0.f;

    issue_chunk_s(0, tid, m0, nt0, bh, sb, Qhi, Qlo, Khi, Klo);
    issue_chunk_s(1, tid, m0, nt0, bh, sb, Qhi, Qlo, Khi, Klo);

    const int warp_m = wid & 3, warp_n = wid >> 2;
    const int rowinA = (lane & 7) + ((lane >> 3) & 1) * 8;
    const int hbA    = lane >> 4;
    const int rowinB = (lane & 7) + ((lane >> 4) & 1) * 8;
    const int hbB    = (lane >> 3) & 1;

    for (int cc = 0; cc < SNCH; cc++) {
        if (cc == SNCH - 1) asm volatile("cp.async.wait_group 0;" ::: "memory");
        else                asm volatile("cp.async.wait_group 1;" ::: "memory");
        __syncthreads();
        if (cc + 2 < SNCH) issue_chunk_s(cc + 2, tid, m0, nt0, bh, sb, Qhi, Qlo, Khi, Klo);

        const uint32_t st = sb + (cc % 3) * SSTAGE_B;
        #pragma unroll
        for (int s = 0; s < 4; s++) {
            uint32_t a[2][4], b[8][2];
            #pragma unroll
            for (int t = 0; t < 2; t++) {
                int r = warp_m * 32 + t * 16 + rowinA;
                uint32_t ad = st + r * 128 + ((((s << 1) | hbA) ^ (r & 7)) << 4);
                ldm4(a[t][0], a[t][1], a[t][2], a[t][3], ad);
            }
            #pragma unroll
            for (int jj = 0; jj < 4; jj++) {
                int r = warp_n * 64 + jj * 16 + rowinB;
                uint32_t ad = st + 16384 + r * 128 + ((((s << 1) | hbB) ^ (r & 7)) << 4);
                ldm4(b[2 * jj][0], b[2 * jj][1], b[2 * jj + 1][0], b[2 * jj + 1][1], ad);
            }
            #pragma unroll
            for (int t = 0; t < 2; t++)
                #pragma unroll
                for (int j = 0; j < 8; j++)
                    mma16816(acc[t][j], a[t], b[j]);
        }
    }

    const float scale = rsqrtf((float)DK_);
    float* Sb = S + (size_t)bh * N_ * N_;
    #pragma unroll
    for (int t = 0; t < 2; t++) {
        const int row0 = m0 + warp_m * 32 + t * 16 + (lane >> 2);
        #pragma unroll
        for (int j = 0; j < 8; j++) {
            const int col = nt0 + warp_n * 64 + j * 8 + (lane & 3) * 2;
            #pragma unroll
            for (int half = 0; half < 2; half++) {
                const int row = row0 + half * 8;
                Sb[(size_t)row * N_ + col]     = acc[t][j][half * 2] * scale;
                Sb[(size_t)row * N_ + col + 1] = acc[t][j][half * 2 + 1] * scale;
            }
        }
    }
}

// ---------------- softmax + head-sum -> attn -------------------------------------
__global__ __launch_bounds__(256) void softmax_kernel(
    const float* __restrict__ S, float* __restrict__ attn)
{
    __shared__ float e[H_][N_];
    __shared__ float winv[H_];

    const int tid = threadIdx.x;
    const int wid = tid >> 5, lane = tid & 31;
    const int ng = blockIdx.x;
    const int b = ng >> 9, n = ng & (N_ - 1);

    if (wid < H_) {
        const float* Sr = S + ((size_t)(b * H_ + wid) * N_ + n) * N_;
        float mx = -FLT_MAX;
        float v[16];
        #pragma unroll
        for (int it = 0; it < 16; it++) {
            v[it] = Sr[lane + it * 32];
            mx = fmaxf(mx, v[it]);
        }
        #pragma unroll
        for (int o = 16; o > 0; o >>= 1) mx = fmaxf(mx, __shfl_xor_sync(0xFFFFFFFFu, mx, o));
        float sum = 0.f;
        #pragma unroll
        for (int it = 0; it < 16; it++) {
            float ex = __expf(v[it] - mx);
            e[wid][lane + it * 32] = ex;
            sum += ex;
        }
        #pragma unroll
        for (int o = 16; o > 0; o >>= 1) sum += __shfl_xor_sync(0xFFFFFFFFu, sum, o);
        if (lane == 0) winv[wid] = __frcp_rn(sum);
    }
    __syncthreads();

    float* an = attn + (size_t)ng * N_;
    for (int m = tid; m < N_; m += 256) {
        float a = 0.f;
        #pragma unroll
        for (int h = 0; h < H_; h++) a += e[h][m] * winv[h];
        an[m] = a;
    }
}

// ---------------- per-batch top-2 threshold + positions -------------------------
__global__ __launch_bounds__(256) void top2_kernel(
    const float* __restrict__ attn, int* __restrict__ pos, int* __restrict__ cnt)
{
    __shared__ float v1s[256], v2s[256];
    __shared__ float s_kth;
    __shared__ int   s_cnt;

    const int b = blockIdx.x;
    const int tid = threadIdx.x;
    const float* A = attn + (size_t)b * N_ * N_;

    float v1 = -FLT_MAX, v2 = -FLT_MAX;
    for (int i = tid; i < N_ * N_; i += 256) {
        float v = A[i];
        if (v > v1) { v2 = v1; v1 = v; }
        else if (v > v2) v2 = v;
    }
    v1s[tid] = v1; v2s[tid] = v2;
    __syncthreads();
    if (tid == 0) {
        float t1 = -FLT_MAX, t2 = -FLT_MAX;
        for (int i = 0; i < 256; i++) {
            float a = v1s[i], c = v2s[i];
            if (a > t1) { t2 = t1; t1 = a; } else if (a > t2) t2 = a;
            if (c > t1) { t2 = t1; t1 = c; } else if (c > t2) t2 = c;
        }
        s_kth = t2;
        s_cnt = 0;
    }
    __syncthreads();
    const float kth = s_kth;
    const int base = b * MAXP * 2;
    for (int i = tid; i < N_ * N_; i += 256) {
        if (A[i] >= kth) {
            int idx = atomicAdd(&s_cnt, 1);
            if (idx < MAXP) {
                pos[base + idx * 2]     = i >> 9;
                pos[base + idx * 2 + 1] = i & (N_ - 1);
            }
        }
    }
    __syncthreads();
    if (tid == 0) {
        int c = s_cnt < MAXP ? s_cnt : MAXP;
        for (int a2 = 1; a2 < c; a2++) {
            int ki = pos[base + a2 * 2], kj = pos[base + a2 * 2 + 1];
            int key = ki * N_ + kj;
            int p = a2 - 1;
            while (p >= 0) {
                int pi = pos[base + p * 2], pj = pos[base + p * 2 + 1];
                if (pi * N_ + pj <= key) break;
                pos[base + (p + 1) * 2] = pi;
                pos[base + (p + 1) * 2 + 1] = pj;
                p--;
            }
            pos[base + (p + 1) * 2] = ki;
            pos[base + (p + 1) * 2 + 1] = kj;
        }
        cnt[b] = c;
    }
}

// ---------------- sparse adjacency apply + GC epilogue --------------------------
__global__ __launch_bounds__(256) void out_kernel(
    const float* __restrict__ attn, const float* __restrict__ hidden,
    const float* __restrict__ bgc, const int* __restrict__ pos,
    const int* __restrict__ cnt, float* __restrict__ out)
{
    const int b = blockIdx.y;
    const int n = blockIdx.x;
    const int tid = threadIdx.x;

    __shared__ int   s_nc;
    __shared__ int   s_cols[2 * MAXP];
    __shared__ float s_w[2 * MAXP];
    __shared__ float s_wd, s_inv;

    if (tid == 0) {
        const float* An = attn + ((size_t)b * N_ + n) * N_;
        const int base = b * MAXP * 2;
        int c = cnt[b];
        int nc = 0;
        float wd = An[n];
        float sum = wd;
        for (int e = 0; e < c; e++) {
            int i = pos[base + e * 2], j = pos[base + e * 2 + 1];
            if (i == n && j != n) { float w = An[j]; s_cols[nc] = j; s_w[nc] = w; sum += w; nc++; }
            if (j == n && i != n) { float w = An[i]; s_cols[nc] = i; s_w[nc] = w; sum += w; nc++; }
        }
        s_nc = nc; s_wd = wd; s_inv = 1.f / (sum + 1.f);
    }
    __syncthreads();

    const int nc = s_nc;
    const float wd = s_wd, inv = s_inv;
    const float* hn = hidden + ((size_t)b * N_ + n) * D_;
    float* on = out + ((size_t)b * N_ + n) * D_;

    for (int d = tid; d < D_; d += 256) {
        float v = wd * hn[d];
        for (int e = 0; e < nc; e++)
            v += s_w[e] * hidden[((size_t)b * N_ + s_cols[e]) * D_ + d];
        v = v * inv + __ldg(&bgc[d]);
        on[d] = fmaxf(v, 0.f);
    }
}

// ---------------- launch ------------------------------------------------------
extern "C" void kernel_launch(void* const* d_in, const int* in_sizes, int n_in,
                              void* d_out, int out_size)
{
    const float* fuse = (const float*)d_in[0];
    const float* Wq   = (const float*)d_in[1];
    const float* bq   = (const float*)d_in[2];
    const float* Wk   = (const float*)d_in[3];
    const float* bk   = (const float*)d_in[4];
    const float* Wgc  = (const float*)d_in[5];
    const float* bgc  = (const float*)d_in[6];
    float* out = (float*)d_out;

    __half *Ahi, *Bh, *Qhi, *Qlo, *Khi, *Klo;
    float *q, *k, *hid, *attn, *S;
    int *pos, *cnt;
    cudaGetSymbolAddress((void**)&Ahi,  g_Ahi);
    cudaGetSymbolAddress((void**)&Bh,   g_Bh);
    cudaGetSymbolAddress((void**)&Qhi,  g_Qhi);
    cudaGetSymbolAddress((void**)&Qlo,  g_Qlo);
    cudaGetSymbolAddress((void**)&Khi,  g_Khi);
    cudaGetSymbolAddress((void**)&Klo,  g_Klo);
    cudaGetSymbolAddress((void**)&S,    g_S);
    cudaGetSymbolAddress((void**)&q,    g_q);
    cudaGetSymbolAddress((void**)&k,    g_k);
    cudaGetSymbolAddress((void**)&hid,  g_h);
    cudaGetSymbolAddress((void**)&attn, g_attn);
    cudaGetSymbolAddress((void**)&pos,  g_pos);
    cudaGetSymbolAddress((void**)&cnt,  g_cnt);

    // 0) fp16 conversions: A hi-only (vectorized); B via zero-fill + transpose
    convA_kernel<<<(M_ * KP_ / 4 + 255) / 256, 256>>>(fuse, Ahi);
    zeroB_kernel<<<(NPAD_ * KP_ / 8 + 255) / 256, 256>>>(Bh);
    transB_kernel<<<dim3(KP_ / 32, (D_ + 31) / 32, 3), 256>>>(Wq, Wk, Wgc, Bh);

    // 1) fused HMMA GEMM (hi term only, 2 CTA/SM) -> q, k, hidden
    cudaFuncSetAttribute(gemm_hmma_kernel, cudaFuncAttributeMaxDynamicSharedMemorySize, GEMM_SMEM);
    gemm_hmma_kernel<<<dim3(NPAD_ / 128, M_ / 128), 256, GEMM_SMEM>>>(
        Ahi, Bh, bq, bk, q, k, hid);

    // 2) pack q/k head-padded fp16 hi/lo (vectorized)
    pack_qk_kernel<<<(BHN * 16 + 255) / 256, 256>>>(q, k, Qhi, Qlo, Khi, Klo);

    // 3) HMMA score GEMM (2 CTA/SM) -> S[B,H,N,N]
    cudaFuncSetAttribute(score_hmma_kernel, cudaFuncAttributeMaxDynamicSharedMemorySize, SGEMM_SMEM);
    score_hmma_kernel<<<dim3(N_ / 128, N_ / 128, B_ * H_), 256, SGEMM_SMEM>>>(
        Qhi, Qlo, Khi, Klo, S);

    // 4) softmax + head-sum -> attn
    softmax_kernel<<<M_, 256>>>(S, attn);

    // 5) per-batch top-2 threshold + sparse positions
    top2_kernel<<<B_, 256>>>(attn, pos, cnt);

    // 6) sparse adjacency apply + graph-conv epilogue
    out_kernel<<<dim3(N_, B_), 256>>>(attn, hid, bgc, pos, cnt, out);
}

// round 10
// speedup vs baseline: 1.6218x; 1.0633x over previous
#include <cuda_runtime.h>
#include <cuda_fp16.h>
#include <cfloat>
#include <cstdint>

// Problem constants
#define B_   32
#define N_   512
#define D_   791
#define H_   7
#define DK_  113
#define M_   (B_ * N_)     // 16384
#define MAXP 64

// main HMMA GEMM: CTA 128x128, warp tile 32x64, 8 warps, 3-stage, 2 CTA/SM
#define KP_     832          // padded K (13 * 64)
#define NCH     13           // single hi term, 13 chunks of K=64
#define NPAD_   2432         // fused N = 3*791 = 2373 padded to 19*128
#define STAGE_B 32768        // A 128x64 fp16 (16KB) + B 128x64 fp16 (16KB)
#define GEMM_SMEM (3 * STAGE_B + 256)
#define BHN (B_ * H_ * N_)   // 114688 packed rows

// score GEMM: CTA 128x128, warp tile 32x64, K = 2 terms x 128 (4 chunks), 3-stage
#define SKP   128
#define SNCH  4
#define SSTAGE_B 32768
#define SGEMM_SMEM (3 * SSTAGE_B + 256)

// ---------------- scratch (device globals; no allocation allowed) -------------
__device__ __align__(256) __half g_Ahi[M_ * KP_];
__device__ __align__(256) __half g_Bh [NPAD_ * KP_];
__device__ __align__(256) __half g_Qhi[(size_t)BHN * SKP];
__device__ __align__(256) __half g_Qlo[(size_t)BHN * SKP];
__device__ __align__(256) __half g_Khi[(size_t)BHN * SKP];
__device__ float g_S[(size_t)B_ * H_ * N_ * N_];
__device__ float g_q[M_ * D_];
__device__ float g_k[M_ * D_];
__device__ float g_h[M_ * D_];
__device__ float g_attn[B_ * N_ * N_];
__device__ int   g_pos[B_ * MAXP * 2];
__device__ int   g_cnt[B_];

// ---------------- PTX helpers --------------------------------------------------
__device__ __forceinline__ uint32_t smem_u32(const void* p) {
    uint32_t a;
    asm("{ .reg .u64 t; cvta.to.shared.u64 t, %1; cvt.u32.u64 %0, t; }" : "=r"(a) : "l"(p));
    return a;
}
__device__ __forceinline__ void ldm4(uint32_t& r0, uint32_t& r1, uint32_t& r2,
                                     uint32_t& r3, uint32_t a) {
    asm volatile("ldmatrix.sync.aligned.m8n8.x4.shared.b16 {%0,%1,%2,%3}, [%4];"
                 : "=r"(r0), "=r"(r1), "=r"(r2), "=r"(r3) : "r"(a));
}
__device__ __forceinline__ void mma16816(float* d, const uint32_t* a, const uint32_t* b) {
    asm volatile(
        "mma.sync.aligned.m16n8k16.row.col.f32.f16.f16.f32 "
        "{%0,%1,%2,%3}, {%4,%5,%6,%7}, {%8,%9}, {%0,%1,%2,%3};"
        : "+f"(d[0]), "+f"(d[1]), "+f"(d[2]), "+f"(d[3])
        : "r"(a[0]), "r"(a[1]), "r"(a[2]), "r"(a[3]), "r"(b[0]), "r"(b[1]));
}
__device__ __forceinline__ void cpa16(uint32_t dst, const void* src) {
    asm volatile("cp.async.cg.shared.global [%0], [%1], 16;" :: "r"(dst), "l"(src));
}

// ---------------- conversions ----------------------------------------------------
__global__ __launch_bounds__(256) void convA_kernel(
    const float* __restrict__ fuse, __half* __restrict__ Ahi)
{
    int idx = blockIdx.x * 256 + threadIdx.x;      // over M_*KP_/4
    if (idx >= M_ * KP_ / 4) return;
    int m = idx / (KP_ / 4);
    int k = (idx - m * (KP_ / 4)) * 4;
    const float* src = fuse + (size_t)m * D_ + k;
    float x0 = (k     < D_) ? __ldg(src)     : 0.f;
    float x1 = (k + 1 < D_) ? __ldg(src + 1) : 0.f;
    float x2 = (k + 2 < D_) ? __ldg(src + 2) : 0.f;
    float x3 = (k + 3 < D_) ? __ldg(src + 3) : 0.f;
    __half2 h01 = __floats2half2_rn(x0, x1);
    __half2 h23 = __floats2half2_rn(x2, x3);
    uint2 o;
    o.x = *reinterpret_cast<uint32_t*>(&h01);
    o.y = *reinterpret_cast<uint32_t*>(&h23);
    *reinterpret_cast<uint2*>(Ahi + (size_t)idx * 4) = o;
}

__global__ __launch_bounds__(256) void zeroB_kernel(__half* __restrict__ Bh)
{
    int idx = blockIdx.x * 256 + threadIdx.x;      // over NPAD_*KP_/8
    if (idx * 8 >= NPAD_ * KP_) return;
    *reinterpret_cast<uint4*>(Bh + idx * 8) = make_uint4(0, 0, 0, 0);
}

// Coalesced transpose: Bh[z*791 + n][k] = W_z[k][n], 32x32 smem tiles.
__global__ __launch_bounds__(256) void transB_kernel(
    const float* __restrict__ Wq, const float* __restrict__ Wk,
    const float* __restrict__ Wgc, __half* __restrict__ Bh)
{
    __shared__ __half tile[32][33];
    const int z = blockIdx.z;
    const float* W = (z == 0) ? Wq : (z == 1) ? Wk : Wgc;
    const int k0 = blockIdx.x * 32;
    const int n0 = blockIdx.y * 32;
    const int tx = threadIdx.x & 31, ty = threadIdx.x >> 5;

    #pragma unroll
    for (int rr = 0; rr < 4; rr++) {
        int k = k0 + ty + rr * 8;
        int n = n0 + tx;
        float v = (k < D_ && n < D_) ? W[(size_t)k * D_ + n] : 0.f;
        tile[ty + rr * 8][tx] = __float2half_rn(v);
    }
    __syncthreads();
    #pragma unroll
    for (int rr = 0; rr < 4; rr++) {
        int n = n0 + ty + rr * 8;
        int k = k0 + tx;
        if (n < D_ && k < KP_)
            Bh[(size_t)(z * D_ + n) * KP_ + k] = tile[tx][ty + rr * 8];
    }
}

// ---------------- HMMA fused GEMM (single hi term, 128x128, 3-stage) -------------
__device__ __forceinline__ void issue_chunk(
    int cc, int tid, int m0, int nt0, uint32_t sb,
    const __half* __restrict__ Ahi, const __half* __restrict__ Bh)
{
    const int kk0 = cc * 64;
    const uint32_t st = sb + (cc % 3) * STAGE_B;
    #pragma unroll
    for (int it = 0; it < 4; it++) {               // A: 1024 x 16B
        int i = tid + it * 256;
        int r = i >> 3, u = i & 7;
        const __half* src = Ahi + (size_t)(m0 + r) * KP_ + kk0 + u * 8;
        cpa16(st + r * 128 + (((u ^ (r & 7))) << 4), src);
    }
    #pragma unroll
    for (int it = 0; it < 4; it++) {               // B: 1024 x 16B
        int i = tid + it * 256;
        int r = i >> 3, u = i & 7;
        const __half* src = Bh + (size_t)(nt0 + r) * KP_ + kk0 + u * 8;
        cpa16(st + 16384 + r * 128 + (((u ^ (r & 7))) << 4), src);
    }
    asm volatile("cp.async.commit_group;" ::: "memory");
}

__global__ __launch_bounds__(256, 2) void gemm_hmma_kernel(
    const __half* __restrict__ Ahi, const __half* __restrict__ Bh,
    const float* __restrict__ bq, const float* __restrict__ bk,
    float* __restrict__ q, float* __restrict__ kk, float* __restrict__ hid)
{
    extern __shared__ char smc[];
    const uint32_t sb = (smem_u32(smc) + 127) & ~127u;
    const int tid = threadIdx.x;
    const int wid = tid >> 5, lane = tid & 31;
    const int m0 = blockIdx.y * 128;
    const int nt0 = blockIdx.x * 128;

    float acc[2][8][4];
    #pragma unroll
    for (int t = 0; t < 2; t++)
        #pragma unroll
        for (int j = 0; j < 8; j++)
            #pragma unroll
            for (int e = 0; e < 4; e++) acc[t][j][e] = 0.f;

    issue_chunk(0, tid, m0, nt0, sb, Ahi, Bh);
    issue_chunk(1, tid, m0, nt0, sb, Ahi, Bh);

    const int warp_m = wid & 3, warp_n = wid >> 2;
    const int rowinA = (lane & 7) + ((lane >> 3) & 1) * 8;
    const int hbA    = lane >> 4;
    const int rowinB = (lane & 7) + ((lane >> 4) & 1) * 8;
    const int hbB    = (lane >> 3) & 1;

    for (int cc = 0; cc < NCH; cc++) {
        if (cc == NCH - 1) asm volatile("cp.async.wait_group 0;" ::: "memory");
        else               asm volatile("cp.async.wait_group 1;" ::: "memory");
        __syncthreads();
        if (cc + 2 < NCH) issue_chunk(cc + 2, tid, m0, nt0, sb, Ahi, Bh);

        const uint32_t st = sb + (cc % 3) * STAGE_B;
        #pragma unroll
        for (int s = 0; s < 4; s++) {
            uint32_t a[2][4], b[8][2];
            #pragma unroll
            for (int t = 0; t < 2; t++) {
                int r = warp_m * 32 + t * 16 + rowinA;
                uint32_t ad = st + r * 128 + ((((s << 1) | hbA) ^ (r & 7)) << 4);
                ldm4(a[t][0], a[t][1], a[t][2], a[t][3], ad);
            }
            #pragma unroll
            for (int jj = 0; jj < 4; jj++) {
                int r = warp_n * 64 + jj * 16 + rowinB;
                uint32_t ad = st + 16384 + r * 128 + ((((s << 1) | hbB) ^ (r & 7)) << 4);
                ldm4(b[2 * jj][0], b[2 * jj][1], b[2 * jj + 1][0], b[2 * jj + 1][1], ad);
            }
            #pragma unroll
            for (int t = 0; t < 2; t++)
                #pragma unroll
                for (int j = 0; j < 8; j++)
                    mma16816(acc[t][j], a[t], b[j]);
        }
    }

    // epilogue: demux to q | k | hid with bias (contiguous fp32 stores)
    #pragma unroll
    for (int t = 0; t < 2; t++) {
        const int row0 = m0 + warp_m * 32 + t * 16 + (lane >> 2);
        #pragma unroll
        for (int j = 0; j < 8; j++) {
            const int col = nt0 + warp_n * 64 + j * 8 + (lane & 3) * 2;
            #pragma unroll
            for (int half = 0; half < 2; half++) {
                const int row = row0 + half * 8;
                const float v0 = acc[t][j][half * 2];
                const float v1 = acc[t][j][half * 2 + 1];
                #pragma unroll
                for (int e = 0; e < 2; e++) {
                    const int c = col + e;
                    const float v = e ? v1 : v0;
                    if (c < D_)
                        q[(size_t)row * D_ + c] = v + __ldg(&bq[c]);
                    else if (c < 2 * D_)
                        kk[(size_t)row * D_ + (c - D_)] = v + __ldg(&bk[c - D_]);
                    else if (c < 3 * D_)
                        hid[(size_t)row * D_ + (c - 2 * D_)] = v;
                }
            }
        }
    }
}

// ---------------- pack q/k: q -> hi/lo, k -> hi only (8 elems/thread) -----------
__global__ __launch_bounds__(256) void pack_qk_kernel(
    const float* __restrict__ q, const float* __restrict__ k,
    __half* __restrict__ Qhi, __half* __restrict__ Qlo, __half* __restrict__ Khi)
{
    int idx = blockIdx.x * 256 + threadIdx.x;      // over BHN*16 (8 elems each)
    if (idx >= BHN * 16) return;
    const int dk0 = (idx & 15) * 8;
    const int rest = idx >> 4;
    const int n = rest & (N_ - 1);
    const int bh = rest >> 9;
    const int h = bh % H_, b = bh / H_;
    const size_t off = ((size_t)(b * N_ + n)) * D_ + h * DK_;

    uint32_t qh[4], ql[4], kh[4];
    #pragma unroll
    for (int p = 0; p < 4; p++) {
        float qv0 = 0.f, qv1 = 0.f, kv0 = 0.f, kv1 = 0.f;
        int d0 = dk0 + p * 2, d1 = d0 + 1;
        if (d0 < DK_) { qv0 = __ldg(&q[off + d0]); kv0 = __ldg(&k[off + d0]); }
        if (d1 < DK_) { qv1 = __ldg(&q[off + d1]); kv1 = __ldg(&k[off + d1]); }
        __half2 qh2 = __floats2half2_rn(qv0, qv1);
        __half2 kh2 = __floats2half2_rn(kv0, kv1);
        __half2 ql2 = __floats2half2_rn(qv0 - __half2float(__low2half(qh2)),
                                        qv1 - __half2float(__high2half(qh2)));
        qh[p] = *reinterpret_cast<uint32_t*>(&qh2);
        ql[p] = *reinterpret_cast<uint32_t*>(&ql2);
        kh[p] = *reinterpret_cast<uint32_t*>(&kh2);
    }
    const size_t dst = (size_t)idx * 8;
    *reinterpret_cast<uint4*>(Qhi + dst) = make_uint4(qh[0], qh[1], qh[2], qh[3]);
    *reinterpret_cast<uint4*>(Qlo + dst) = make_uint4(ql[0], ql[1], ql[2], ql[3]);
    *reinterpret_cast<uint4*>(Khi + dst) = make_uint4(kh[0], kh[1], kh[2], kh[3]);
}

// ---------------- HMMA score GEMM (2 terms, 3-stage, 2 CTA/SM) -------------------
// S[bh] = (Qhi + Qlo) @ Khi^T, scaled by 1/sqrt(113).
__device__ __forceinline__ void issue_chunk_s(
    int cc, int tid, int m0, int nt0, int bh, uint32_t sb,
    const __half* __restrict__ Qhi, const __half* __restrict__ Qlo,
    const __half* __restrict__ Khi)
{
    const int kk0 = (cc & 1) * 64;
    const __half* As = (cc >= 2) ? Qlo : Qhi;
    const size_t base = (size_t)bh * N_ * SKP;
    const uint32_t st = sb + (cc % 3) * SSTAGE_B;
    #pragma unroll
    for (int it = 0; it < 4; it++) {               // A: 1024 x 16B
        int i = tid + it * 256;
        int r = i >> 3, u = i & 7;
        const __half* src = As + base + (size_t)(m0 + r) * SKP + kk0 + u * 8;
        cpa16(st + r * 128 + (((u ^ (r & 7))) << 4), src);
    }
    #pragma unroll
    for (int it = 0; it < 4; it++) {               // B: 1024 x 16B
        int i = tid + it * 256;
        int r = i >> 3, u = i & 7;
        const __half* src = Khi + base + (size_t)(nt0 + r) * SKP + kk0 + u * 8;
        cpa16(st + 16384 + r * 128 + (((u ^ (r & 7))) << 4), src);
    }
    asm volatile("cp.async.commit_group;" ::: "memory");
}

__global__ __launch_bounds__(256, 2) void score_hmma_kernel(
    const __half* __restrict__ Qhi, const __half* __restrict__ Qlo,
    const __half* __restrict__ Khi, float* __restrict__ S)
{
    extern __shared__ char smc[];
    const uint32_t sb = (smem_u32(smc) + 127) & ~127u;
    const int tid = threadIdx.x;
    const int wid = tid >> 5, lane = tid & 31;
    const int m0 = blockIdx.y * 128;
    const int nt0 = blockIdx.x * 128;
    const int bh = blockIdx.z;

    float acc[2][8][4];
    #pragma unroll
    for (int t = 0; t < 2; t++)
        #pragma unroll
        for (int j = 0; j < 8; j++)
            #pragma unroll
            for (int e = 0; e < 4; e++) acc[t][j][e] = 0.f;

    issue_chunk_s(0, tid, m0, nt0, bh, sb, Qhi, Qlo, Khi);
    issue_chunk_s(1, tid, m0, nt0, bh, sb, Qhi, Qlo, Khi);

    const int warp_m = wid & 3, warp_n = wid >> 2;
    const int rowinA = (lane & 7) + ((lane >> 3) & 1) * 8;
    const int hbA    = lane >> 4;
    const int rowinB = (lane & 7) + ((lane >> 4) & 1) * 8;
    const int hbB    = (lane >> 3) & 1;

    for (int cc = 0; cc < SNCH; cc++) {
        if (cc == SNCH - 1) asm volatile("cp.async.wait_group 0;" ::: "memory");
        else                asm volatile("cp.async.wait_group 1;" ::: "memory");
        __syncthreads();
        if (cc + 2 < SNCH) issue_chunk_s(cc + 2, tid, m0, nt0, bh, sb, Qhi, Qlo, Khi);

        const uint32_t st = sb + (cc % 3) * SSTAGE_B;
        #pragma unroll
        for (int s = 0; s < 4; s++) {
            uint32_t a[2][4], b[8][2];
            #pragma unroll
            for (int t = 0; t < 2; t++) {
                int r = warp_m * 32 + t * 16 + rowinA;
                uint32_t ad = st + r * 128 + ((((s << 1) | hbA) ^ (r & 7)) << 4);
                ldm4(a[t][0], a[t][1], a[t][2], a[t][3], ad);
            }
            #pragma unroll
            for (int jj = 0; jj < 4; jj++) {
                int r = warp_n * 64 + jj * 16 + rowinB;
                uint32_t ad = st + 16384 + r * 128 + ((((s << 1) | hbB) ^ (r & 7)) << 4);
                ldm4(b[2 * jj][0], b[2 * jj][1], b[2 * jj + 1][0], b[2 * jj + 1][1], ad);
            }
            #pragma unroll
            for (int t = 0; t < 2; t++)
                #pragma unroll
                for (int j = 0; j < 8; j++)
                    mma16816(acc[t][j], a[t], b[j]);
        }
    }

    const float scale = rsqrtf((float)DK_);
    float* Sb = S + (size_t)bh * N_ * N_;
    #pragma unroll
    for (int t = 0; t < 2; t++) {
        const int row0 = m0 + warp_m * 32 + t * 16 + (lane >> 2);
        #pragma unroll
        for (int j = 0; j < 8; j++) {
            const int col = nt0 + warp_n * 64 + j * 8 + (lane & 3) * 2;
            #pragma unroll
            for (int half = 0; half < 2; half++) {
                const int row = row0 + half * 8;
                Sb[(size_t)row * N_ + col]     = acc[t][j][half * 2] * scale;
                Sb[(size_t)row * N_ + col + 1] = acc[t][j][half * 2 + 1] * scale;
            }
        }
    }
}

// ---------------- softmax + head-sum -> attn -------------------------------------
__global__ __launch_bounds__(256) void softmax_kernel(
    const float* __restrict__ S, float* __restrict__ attn)
{
    __shared__ float e[H_][N_];
    __shared__ float winv[H_];

    const int tid = threadIdx.x;
    const int wid = tid >> 5, lane = tid & 31;
    const int ng = blockIdx.x;
    const int b = ng >> 9, n = ng & (N_ - 1);

    if (wid < H_) {
        const float* Sr = S + ((size_t)(b * H_ + wid) * N_ + n) * N_;
        float mx = -FLT_MAX;
        float v[16];
        #pragma unroll
        for (int it = 0; it < 16; it++) {
            v[it] = Sr[lane + it * 32];
            mx = fmaxf(mx, v[it]);
        }
        #pragma unroll
        for (int o = 16; o > 0; o >>= 1) mx = fmaxf(mx, __shfl_xor_sync(0xFFFFFFFFu, mx, o));
        float sum = 0.f;
        #pragma unroll
        for (int it = 0; it < 16; it++) {
            float ex = __expf(v[it] - mx);
            e[wid][lane + it * 32] = ex;
            sum += ex;
        }
        #pragma unroll
        for (int o = 16; o > 0; o >>= 1) sum += __shfl_xor_sync(0xFFFFFFFFu, sum, o);
        if (lane == 0) winv[wid] = __frcp_rn(sum);
    }
    __syncthreads();

    float* an = attn + (size_t)ng * N_;
    for (int m = tid; m < N_; m += 256) {
        float a = 0.f;
        #pragma unroll
        for (int h = 0; h < H_; h++) a += e[h][m] * winv[h];
        an[m] = a;
    }
}

// ---------------- per-batch top-2 threshold + positions -------------------------
__global__ __launch_bounds__(256) void top2_kernel(
    const float* __restrict__ attn, int* __restrict__ pos, int* __restrict__ cnt)
{
    __shared__ float v1s[256], v2s[256];
    __shared__ float s_kth;
    __shared__ int   s_cnt;

    const int b = blockIdx.x;
    const int tid = threadIdx.x;
    const float* A = attn + (size_t)b * N_ * N_;

    float v1 = -FLT_MAX, v2 = -FLT_MAX;
    for (int i = tid; i < N_ * N_; i += 256) {
        float v = A[i];
        if (v > v1) { v2 = v1; v1 = v; }
        else if (v > v2) v2 = v;
    }
    v1s[tid] = v1; v2s[tid] = v2;
    __syncthreads();
    if (tid == 0) {
        float t1 = -FLT_MAX, t2 = -FLT_MAX;
        for (int i = 0; i < 256; i++) {
            float a = v1s[i], c = v2s[i];
            if (a > t1) { t2 = t1; t1 = a; } else if (a > t2) t2 = a;
            if (c > t1) { t2 = t1; t1 = c; } else if (c > t2) t2 = c;
        }
        s_kth = t2;
        s_cnt = 0;
    }
    __syncthreads();
    const float kth = s_kth;
    const int base = b * MAXP * 2;
    for (int i = tid; i < N_ * N_; i += 256) {
        if (A[i] >= kth) {
            int idx = atomicAdd(&s_cnt, 1);
            if (idx < MAXP) {
                pos[base + idx * 2]     = i >> 9;
                pos[base + idx * 2 + 1] = i & (N_ - 1);
            }
        }
    }
    __syncthreads();
    if (tid == 0) {
        int c = s_cnt < MAXP ? s_cnt : MAXP;
        for (int a2 = 1; a2 < c; a2++) {
            int ki = pos[base + a2 * 2], kj = pos[base + a2 * 2 + 1];
            int key = ki * N_ + kj;
            int p = a2 - 1;
            while (p >= 0) {
                int pi = pos[base + p * 2], pj = pos[base + p * 2 + 1];
                if (pi * N_ + pj <= key) break;
                pos[base + (p + 1) * 2] = pi;
                pos[base + (p + 1) * 2 + 1] = pj;
                p--;
            }
            pos[base + (p + 1) * 2] = ki;
            pos[base + (p + 1) * 2 + 1] = kj;
        }
        cnt[b] = c;
    }
}

// ---------------- sparse adjacency apply + GC epilogue --------------------------
__global__ __launch_bounds__(256) void out_kernel(
    const float* __restrict__ attn, const float* __restrict__ hidden,
    const float* __restrict__ bgc, const int* __restrict__ pos,
    const int* __restrict__ cnt, float* __restrict__ out)
{
    const int b = blockIdx.y;
    const int n = blockIdx.x;
    const int tid = threadIdx.x;

    __shared__ int   s_nc;
    __shared__ int   s_cols[2 * MAXP];
    __shared__ float s_w[2 * MAXP];
    __shared__ float s_wd, s_inv;

    if (tid == 0) {
        const float* An = attn + ((size_t)b * N_ + n) * N_;
        const int base = b * MAXP * 2;
        int c = cnt[b];
        int nc = 0;
        float wd = An[n];
        float sum = wd;
        for (int e = 0; e < c; e++) {
            int i = pos[base + e * 2], j = pos[base + e * 2 + 1];
            if (i == n && j != n) { float w = An[j]; s_cols[nc] = j; s_w[nc] = w; sum += w; nc++; }
            if (j == n && i != n) { float w = An[i]; s_cols[nc] = i; s_w[nc] = w; sum += w; nc++; }
        }
        s_nc = nc; s_wd = wd; s_inv = 1.f / (sum + 1.f);
    }
    __syncthreads();

    const int nc = s_nc;
    const float wd = s_wd, inv = s_inv;
    const float* hn = hidden + ((size_t)b * N_ + n) * D_;
    float* on = out + ((size_t)b * N_ + n) * D_;

    for (int d = tid; d < D_; d += 256) {
        float v = wd * hn[d];
        for (int e = 0; e < nc; e++)
            v += s_w[e] * hidden[((size_t)b * N_ + s_cols[e]) * D_ + d];
        v = v * inv + __ldg(&bgc[d]);
        on[d] = fmaxf(v, 0.f);
    }
}

// ---------------- launch ------------------------------------------------------
extern "C" void kernel_launch(void* const* d_in, const int* in_sizes, int n_in,
                              void* d_out, int out_size)
{
    const float* fuse = (const float*)d_in[0];
    const float* Wq   = (const float*)d_in[1];
    const float* bq   = (const float*)d_in[2];
    const float* Wk   = (const float*)d_in[3];
    const float* bk   = (const float*)d_in[4];
    const float* Wgc  = (const float*)d_in[5];
    const float* bgc  = (const float*)d_in[6];
    float* out = (float*)d_out;

    __half *Ahi, *Bh, *Qhi, *Qlo, *Khi;
    float *q, *k, *hid, *attn, *S;
    int *pos, *cnt;
    cudaGetSymbolAddress((void**)&Ahi,  g_Ahi);
    cudaGetSymbolAddress((void**)&Bh,   g_Bh);
    cudaGetSymbolAddress((void**)&Qhi,  g_Qhi);
    cudaGetSymbolAddress((void**)&Qlo,  g_Qlo);
    cudaGetSymbolAddress((void**)&Khi,  g_Khi);
    cudaGetSymbolAddress((void**)&S,    g_S);
    cudaGetSymbolAddress((void**)&q,    g_q);
    cudaGetSymbolAddress((void**)&k,    g_k);
    cudaGetSymbolAddress((void**)&hid,  g_h);
    cudaGetSymbolAddress((void**)&attn, g_attn);
    cudaGetSymbolAddress((void**)&pos,  g_pos);
    cudaGetSymbolAddress((void**)&cnt,  g_cnt);

    // 0) fp16 conversions: A hi-only (vectorized); B via zero-fill + transpose
    convA_kernel<<<(M_ * KP_ / 4 + 255) / 256, 256>>>(fuse, Ahi);
    zeroB_kernel<<<(NPAD_ * KP_ / 8 + 255) / 256, 256>>>(Bh);
    transB_kernel<<<dim3(KP_ / 32, (D_ + 31) / 32, 3), 256>>>(Wq, Wk, Wgc, Bh);

    // 1) fused HMMA GEMM (hi term only, 2 CTA/SM) -> q, k, hidden
    cudaFuncSetAttribute(gemm_hmma_kernel, cudaFuncAttributeMaxDynamicSharedMemorySize, GEMM_SMEM);
    gemm_hmma_kernel<<<dim3(NPAD_ / 128, M_ / 128), 256, GEMM_SMEM>>>(
        Ahi, Bh, bq, bk, q, k, hid);

    // 2) pack q (hi/lo) and k (hi) head-padded fp16 (vectorized)
    pack_qk_kernel<<<(BHN * 16 + 255) / 256, 256>>>(q, k, Qhi, Qlo, Khi);

    // 3) HMMA score GEMM (2 terms, 2 CTA/SM) -> S[B,H,N,N]
    cudaFuncSetAttribute(score_hmma_kernel, cudaFuncAttributeMaxDynamicSharedMemorySize, SGEMM_SMEM);
    score_hmma_kernel<<<dim3(N_ / 128, N_ / 128, B_ * H_), 256, SGEMM_SMEM>>>(
        Qhi, Qlo, Khi, S);

    // 4) softmax + head-sum -> attn
    softmax_kernel<<<M_, 256>>>(S, attn);

    // 5) per-batch top-2 threshold + sparse positions
    top2_kernel<<<B_, 256>>>(attn, pos, cnt);

    // 6) sparse adjacency apply + graph-conv epilogue
    out_kernel<<<dim3(N_, B_), 256>>>(attn, hid, bgc, pos, cnt, out);
}

// round 12
// speedup vs baseline: 1.7016x; 1.0492x over previous
#include <cuda_runtime.h>
#include <cuda_fp16.h>
#include <cfloat>
#include <cstdint>

// Problem constants
#define B_   32
#define N_   512
#define D_   791
#define H_   7
#define DK_  113
#define M_   (B_ * N_)     // 16384
#define MAXP 64

// main HMMA GEMM: CTA 128x128, warp tile 32x64, 8 warps, 3-stage, 2 CTA/SM
#define KP_     832          // padded K (13 * 64)
#define NCH     13           // single hi term, 13 chunks of K=64
#define NPAD_   2432         // fused N = 3*791 = 2373 padded to 19*128
#define STAGE_B 32768        // A 128x64 fp16 (16KB) + B 128x64 fp16 (16KB)
#define GEMM_SMEM (3 * STAGE_B + 256)
#define BHN (B_ * H_ * N_)   // 114688 packed rows

// score GEMM: CTA 128x128, warp tile 32x64, K = 2 terms x 128 (4 chunks), 3-stage
#define SKP   128
#define SNCH  4
#define SSTAGE_B 32768
#define SGEMM_SMEM (3 * SSTAGE_B + 256)
#define EPI_STRIDE 272       // fp16 staging row stride (bytes): 16B-aligned, conflict-free

// ---------------- scratch (device globals; no allocation allowed) -------------
__device__ __align__(256) __half g_Ahi[M_ * KP_];
__device__ __align__(256) __half g_Bh [NPAD_ * KP_];
__device__ __align__(256) __half g_Qhi[(size_t)BHN * SKP];
__device__ __align__(256) __half g_Qlo[(size_t)BHN * SKP];
__device__ __align__(256) __half g_Khi[(size_t)BHN * SKP];
__device__ __align__(256) __half g_S[(size_t)B_ * H_ * N_ * N_];
__device__ float g_q[M_ * D_];
__device__ float g_k[M_ * D_];
__device__ float g_h[M_ * D_];
__device__ float g_attn[B_ * N_ * N_];
__device__ int   g_pos[B_ * MAXP * 2];
__device__ int   g_cnt[B_];

// ---------------- PTX helpers --------------------------------------------------
__device__ __forceinline__ uint32_t smem_u32(const void* p) {
    uint32_t a;
    asm("{ .reg .u64 t; cvta.to.shared.u64 t, %1; cvt.u32.u64 %0, t; }" : "=r"(a) : "l"(p));
    return a;
}
__device__ __forceinline__ void ldm4(uint32_t& r0, uint32_t& r1, uint32_t& r2,
                                     uint32_t& r3, uint32_t a) {
    asm volatile("ldmatrix.sync.aligned.m8n8.x4.shared.b16 {%0,%1,%2,%3}, [%4];"
                 : "=r"(r0), "=r"(r1), "=r"(r2), "=r"(r3) : "r"(a));
}
__device__ __forceinline__ void mma16816(float* d, const uint32_t* a, const uint32_t* b) {
    asm volatile(
        "mma.sync.aligned.m16n8k16.row.col.f32.f16.f16.f32 "
        "{%0,%1,%2,%3}, {%4,%5,%6,%7}, {%8,%9}, {%0,%1,%2,%3};"
        : "+f"(d[0]), "+f"(d[1]), "+f"(d[2]), "+f"(d[3])
        : "r"(a[0]), "r"(a[1]), "r"(a[2]), "r"(a[3]), "r"(b[0]), "r"(b[1]));
}
__device__ __forceinline__ void cpa16(uint32_t dst, const void* src) {
    asm volatile("cp.async.cg.shared.global [%0], [%1], 16;" :: "r"(dst), "l"(src));
}

// ---------------- conversions ----------------------------------------------------
__global__ __launch_bounds__(256) void convA_kernel(
    const float* __restrict__ fuse, __half* __restrict__ Ahi)
{
    int idx = blockIdx.x * 256 + threadIdx.x;      // over M_*KP_/4
    if (idx >= M_ * KP_ / 4) return;
    int m = idx / (KP_ / 4);
    int k = (idx - m * (KP_ / 4)) * 4;
    const float* src = fuse + (size_t)m * D_ + k;
    float x0 = (k     < D_) ? __ldg(src)     : 0.f;
    float x1 = (k + 1 < D_) ? __ldg(src + 1) : 0.f;
    float x2 = (k + 2 < D_) ? __ldg(src + 2) : 0.f;
    float x3 = (k + 3 < D_) ? __ldg(src + 3) : 0.f;
    __half2 h01 = __floats2half2_rn(x0, x1);
    __half2 h23 = __floats2half2_rn(x2, x3);
    uint2 o;
    o.x = *reinterpret_cast<uint32_t*>(&h01);
    o.y = *reinterpret_cast<uint32_t*>(&h23);
    *reinterpret_cast<uint2*>(Ahi + (size_t)idx * 4) = o;
}

__global__ __launch_bounds__(256) void zeroB_kernel(__half* __restrict__ Bh)
{
    int idx = blockIdx.x * 256 + threadIdx.x;      // over NPAD_*KP_/8
    if (idx * 8 >= NPAD_ * KP_) return;
    *reinterpret_cast<uint4*>(Bh + idx * 8) = make_uint4(0, 0, 0, 0);
}

// Coalesced transpose: Bh[z*791 + n][k] = W_z[k][n], 32x32 smem tiles.
__global__ __launch_bounds__(256) void transB_kernel(
    const float* __restrict__ Wq, const float* __restrict__ Wk,
    const float* __restrict__ Wgc, __half* __restrict__ Bh)
{
    __shared__ __half tile[32][33];
    const int z = blockIdx.z;
    const float* W = (z == 0) ? Wq : (z == 1) ? Wk : Wgc;
    const int k0 = blockIdx.x * 32;
    const int n0 = blockIdx.y * 32;
    const int tx = threadIdx.x & 31, ty = threadIdx.x >> 5;

    #pragma unroll
    for (int rr = 0; rr < 4; rr++) {
        int k = k0 + ty + rr * 8;
        int n = n0 + tx;
        float v = (k < D_ && n < D_) ? W[(size_t)k * D_ + n] : 0.f;
        tile[ty + rr * 8][tx] = __float2half_rn(v);
    }
    __syncthreads();
    #pragma unroll
    for (int rr = 0; rr < 4; rr++) {
        int n = n0 + ty + rr * 8;
        int k = k0 + tx;
        if (n < D_ && k < KP_)
            Bh[(size_t)(z * D_ + n) * KP_ + k] = tile[tx][ty + rr * 8];
    }
}

// ---------------- HMMA fused GEMM (single hi term, 128x128, 3-stage) -------------
__device__ __forceinline__ void issue_chunk(
    int cc, int tid, int m0, int nt0, uint32_t sb,
    const __half* __restrict__ Ahi, const __half* __restrict__ Bh)
{
    const int kk0 = cc * 64;
    const uint32_t st = sb + (cc % 3) * STAGE_B;
    #pragma unroll
    for (int it = 0; it < 4; it++) {               // A: 1024 x 16B
        int i = tid + it * 256;
        int r = i >> 3, u = i & 7;
        const __half* src = Ahi + (size_t)(m0 + r) * KP_ + kk0 + u * 8;
        cpa16(st + r * 128 + (((u ^ (r & 7))) << 4), src);
    }
    #pragma unroll
    for (int it = 0; it < 4; it++) {               // B: 1024 x 16B
        int i = tid + it * 256;
        int r = i >> 3, u = i & 7;
        const __half* src = Bh + (size_t)(nt0 + r) * KP_ + kk0 + u * 8;
        cpa16(st + 16384 + r * 128 + (((u ^ (r & 7))) << 4), src);
    }
    asm volatile("cp.async.commit_group;" ::: "memory");
}

__global__ __launch_bounds__(256, 2) void gemm_hmma_kernel(
    const __half* __restrict__ Ahi, const __half* __restrict__ Bh,
    const float* __restrict__ bq, const float* __restrict__ bk,
    float* __restrict__ q, float* __restrict__ kk, float* __restrict__ hid)
{
    extern __shared__ char smc[];
    const uint32_t sb = (smem_u32(smc) + 127) & ~127u;
    const int tid = threadIdx.x;
    const int wid = tid >> 5, lane = tid & 31;
    const int m0 = blockIdx.y * 128;
    const int nt0 = blockIdx.x * 128;

    float acc[2][8][4];
    #pragma unroll
    for (int t = 0; t < 2; t++)
        #pragma unroll
        for (int j = 0; j < 8; j++)
            #pragma unroll
            for (int e = 0; e < 4; e++) acc[t][j][e] = 0.f;

    issue_chunk(0, tid, m0, nt0, sb, Ahi, Bh);
    issue_chunk(1, tid, m0, nt0, sb, Ahi, Bh);

    const int warp_m = wid & 3, warp_n = wid >> 2;
    const int rowinA = (lane & 7) + ((lane >> 3) & 1) * 8;
    const int hbA    = lane >> 4;
    const int rowinB = (lane & 7) + ((lane >> 4) & 1) * 8;
    const int hbB    = (lane >> 3) & 1;

    for (int cc = 0; cc < NCH; cc++) {
        if (cc == NCH - 1) asm volatile("cp.async.wait_group 0;" ::: "memory");
        else               asm volatile("cp.async.wait_group 1;" ::: "memory");
        __syncthreads();
        if (cc + 2 < NCH) issue_chunk(cc + 2, tid, m0, nt0, sb, Ahi, Bh);

        const uint32_t st = sb + (cc % 3) * STAGE_B;
        #pragma unroll
        for (int s = 0; s < 4; s++) {
            uint32_t a[2][4], b[8][2];
            #pragma unroll
            for (int t = 0; t < 2; t++) {
                int r = warp_m * 32 + t * 16 + rowinA;
                uint32_t ad = st + r * 128 + ((((s << 1) | hbA) ^ (r & 7)) << 4);
                ldm4(a[t][0], a[t][1], a[t][2], a[t][3], ad);
            }
            #pragma unroll
            for (int jj = 0; jj < 4; jj++) {
                int r = warp_n * 64 + jj * 16 + rowinB;
                uint32_t ad = st + 16384 + r * 128 + ((((s << 1) | hbB) ^ (r & 7)) << 4);
                ldm4(b[2 * jj][0], b[2 * jj][1], b[2 * jj + 1][0], b[2 * jj + 1][1], ad);
            }
            #pragma unroll
            for (int t = 0; t < 2; t++)
                #pragma unroll
                for (int j = 0; j < 8; j++)
                    mma16816(acc[t][j], a[t], b[j]);
        }
    }

    // epilogue: demux to q | k | hid with bias (contiguous fp32 stores)
    #pragma unroll
    for (int t = 0; t < 2; t++) {
        const int row0 = m0 + warp_m * 32 + t * 16 + (lane >> 2);
        #pragma unroll
        for (int j = 0; j < 8; j++) {
            const int col = nt0 + warp_n * 64 + j * 8 + (lane & 3) * 2;
            #pragma unroll
            for (int half = 0; half < 2; half++) {
                const int row = row0 + half * 8;
                const float v0 = acc[t][j][half * 2];
                const float v1 = acc[t][j][half * 2 + 1];
                #pragma unroll
                for (int e = 0; e < 2; e++) {
                    const int c = col + e;
                    const float v = e ? v1 : v0;
                    if (c < D_)
                        q[(size_t)row * D_ + c] = v + __ldg(&bq[c]);
                    else if (c < 2 * D_)
                        kk[(size_t)row * D_ + (c - D_)] = v + __ldg(&bk[c - D_]);
                    else if (c < 3 * D_)
                        hid[(size_t)row * D_ + (c - 2 * D_)] = v;
                }
            }
        }
    }
}

// ---------------- pack q/k: q -> hi/lo, k -> hi only (8 elems/thread) -----------
__global__ __launch_bounds__(256) void pack_qk_kernel(
    const float* __restrict__ q, const float* __restrict__ k,
    __half* __restrict__ Qhi, __half* __restrict__ Qlo, __half* __restrict__ Khi)
{
    int idx = blockIdx.x * 256 + threadIdx.x;      // over BHN*16 (8 elems each)
    if (idx >= BHN * 16) return;
    const int dk0 = (idx & 15) * 8;
    const int rest = idx >> 4;
    const int n = rest & (N_ - 1);
    const int bh = rest >> 9;
    const int h = bh % H_, b = bh / H_;
    const size_t off = ((size_t)(b * N_ + n)) * D_ + h * DK_;

    uint32_t qh[4], ql[4], kh[4];
    #pragma unroll
    for (int p = 0; p < 4; p++) {
        float qv0 = 0.f, qv1 = 0.f, kv0 = 0.f, kv1 = 0.f;
        int d0 = dk0 + p * 2, d1 = d0 + 1;
        if (d0 < DK_) { qv0 = __ldg(&q[off + d0]); kv0 = __ldg(&k[off + d0]); }
        if (d1 < DK_) { qv1 = __ldg(&q[off + d1]); kv1 = __ldg(&k[off + d1]); }
        __half2 qh2 = __floats2half2_rn(qv0, qv1);
        __half2 kh2 = __floats2half2_rn(kv0, kv1);
        __half2 ql2 = __floats2half2_rn(qv0 - __half2float(__low2half(qh2)),
                                        qv1 - __half2float(__high2half(qh2)));
        qh[p] = *reinterpret_cast<uint32_t*>(&qh2);
        ql[p] = *reinterpret_cast<uint32_t*>(&ql2);
        kh[p] = *reinterpret_cast<uint32_t*>(&kh2);
    }
    const size_t dst = (size_t)idx * 8;
    *reinterpret_cast<uint4*>(Qhi + dst) = make_uint4(qh[0], qh[1], qh[2], qh[3]);
    *reinterpret_cast<uint4*>(Qlo + dst) = make_uint4(ql[0], ql[1], ql[2], ql[3]);
    *reinterpret_cast<uint4*>(Khi + dst) = make_uint4(kh[0], kh[1], kh[2], kh[3]);
}

// ---------------- HMMA score GEMM (2 terms, 3-stage, fp16 output) ----------------
// S[bh] = (Qhi + Qlo) @ Khi^T, scaled by 1/sqrt(113), stored fp16 via smem staging.
__device__ __forceinline__ void issue_chunk_s(
    int cc, int tid, int m0, int nt0, int bh, uint32_t sb,
    const __half* __restrict__ Qhi, const __half* __restrict__ Qlo,
    const __half* __restrict__ Khi)
{
    const int kk0 = (cc & 1) * 64;
    const __half* As = (cc >= 2) ? Qlo : Qhi;
    const size_t base = (size_t)bh * N_ * SKP;
    const uint32_t st = sb + (cc % 3) * SSTAGE_B;
    #pragma unroll
    for (int it = 0; it < 4; it++) {               // A: 1024 x 16B
        int i = tid + it * 256;
        int r = i >> 3, u = i & 7;
        const __half* src = As + base + (size_t)(m0 + r) * SKP + kk0 + u * 8;
        cpa16(st + r * 128 + (((u ^ (r & 7))) << 4), src);
    }
    #pragma unroll
    for (int it = 0; it < 4; it++) {               // B: 1024 x 16B
        int i = tid + it * 256;
        int r = i >> 3, u = i & 7;
        const __half* src = Khi + base + (size_t)(nt0 + r) * SKP + kk0 + u * 8;
        cpa16(st + 16384 + r * 128 + (((u ^ (r & 7))) << 4), src);
    }
    asm volatile("cp.async.commit_group;" ::: "memory");
}

__global__ __launch_bounds__(256, 2) void score_hmma_kernel(
    const __half* __restrict__ Qhi, const __half* __restrict__ Qlo,
    const __half* __restrict__ Khi, __half* __restrict__ S)
{
    extern __shared__ char smc[];
    char* smb = (char*)(((uintptr_t)smc + 127) & ~(uintptr_t)127);
    const uint32_t sb = smem_u32(smb);
    const int tid = threadIdx.x;
    const int wid = tid >> 5, lane = tid & 31;
    const int m0 = blockIdx.y * 128;
    const int nt0 = blockIdx.x * 128;
    const int bh = blockIdx.z;

    float acc[2][8][4];
    #pragma unroll
    for (int t = 0; t < 2; t++)
        #pragma unroll
        for (int j = 0; j < 8; j++)
            #pragma unroll
            for (int e = 0; e < 4; e++) acc[t][j][e] = 0.f;

    issue_chunk_s(0, tid, m0, nt0, bh, sb, Qhi, Qlo, Khi);
    issue_chunk_s(1, tid, m0, nt0, bh, sb, Qhi, Qlo, Khi);

    const int warp_m = wid & 3, warp_n = wid >> 2;
    const int rowinA = (lane & 7) + ((lane >> 3) & 1) * 8;
    const int hbA    = lane >> 4;
    const int rowinB = (lane & 7) + ((lane >> 4) & 1) * 8;
    const int hbB    = (lane >> 3) & 1;

    for (int cc = 0; cc < SNCH; cc++) {
        if (cc == SNCH - 1) asm volatile("cp.async.wait_group 0;" ::: "memory");
        else                asm volatile("cp.async.wait_group 1;" ::: "memory");
        __syncthreads();
        if (cc + 2 < SNCH) issue_chunk_s(cc + 2, tid, m0, nt0, bh, sb, Qhi, Qlo, Khi);

        const uint32_t st = sb + (cc % 3) * SSTAGE_B;
        #pragma unroll
        for (int s = 0; s < 4; s++) {
            uint32_t a[2][4], b[8][2];
            #pragma unroll
            for (int t = 0; t < 2; t++) {
                int r = warp_m * 32 + t * 16 + rowinA;
                uint32_t ad = st + r * 128 + ((((s << 1) | hbA) ^ (r & 7)) << 4);
                ldm4(a[t][0], a[t][1], a[t][2], a[t][3], ad);
            }
            #pragma unroll
            for (int jj = 0; jj < 4; jj++) {
                int r = warp_n * 64 + jj * 16 + rowinB;
                uint32_t ad = st + 16384 + r * 128 + ((((s << 1) | hbB) ^ (r & 7)) << 4);
                ldm4(b[2 * jj][0], b[2 * jj][1], b[2 * jj + 1][0], b[2 * jj + 1][1], ad);
            }
            #pragma unroll
            for (int t = 0; t < 2; t++)
                #pragma unroll
                for (int j = 0; j < 8; j++)
                    mma16816(acc[t][j], a[t], b[j]);
        }
    }

    // ---- fp16 epilogue: stage 128x128 half tile in smem, write coalesced ----
    __syncthreads();                       // all warps done reading stage buffers
    const float scale = rsqrtf((float)DK_);
    #pragma unroll
    for (int t = 0; t < 2; t++) {
        const int rl0 = warp_m * 32 + t * 16 + (lane >> 2);
        #pragma unroll
        for (int j = 0; j < 8; j++) {
            const int cl = warp_n * 64 + j * 8 + (lane & 3) * 2;
            #pragma unroll
            for (int half = 0; half < 2; half++) {
                const int rl = rl0 + half * 8;
                __half2 hv = __floats2half2_rn(acc[t][j][half * 2] * scale,
                                               acc[t][j][half * 2 + 1] * scale);
                *reinterpret_cast<uint32_t*>(smb + rl * EPI_STRIDE + cl * 2) =
                    *reinterpret_cast<uint32_t*>(&hv);
            }
        }
    }
    __syncthreads();

    // 256 threads x (1 row-half of 128B each): fully coalesced fp16 stores
    {
        const int row = tid >> 1, seg = tid & 1;
        const char* src = smb + row * EPI_STRIDE + seg * 128;
        __half* dst = S + (size_t)bh * N_ * N_ + (size_t)(m0 + row) * N_ + nt0 + seg * 64;
        #pragma unroll
        for (int u = 0; u < 8; u++)
            *reinterpret_cast<uint4*>(dst + u * 8) =
                *reinterpret_cast<const uint4*>(src + u * 16);
    }
}

// ---------------- softmax + head-sum -> attn (fp16 S input) ----------------------
__global__ __launch_bounds__(256) void softmax_kernel(
    const __half* __restrict__ S, float* __restrict__ attn)
{
    __shared__ float e[H_][N_];
    __shared__ float winv[H_];

    const int tid = threadIdx.x;
    const int wid = tid >> 5, lane = tid & 31;
    const int ng = blockIdx.x;
    const int b = ng >> 9, n = ng & (N_ - 1);

    if (wid < H_) {
        const __half2* Sr2 = reinterpret_cast<const __half2*>(
            S + ((size_t)(b * H_ + wid) * N_ + n) * N_);
        float v[16];
        float mx = -FLT_MAX;
        #pragma unroll
        for (int it = 0; it < 8; it++) {
            float2 f = __half22float2(Sr2[lane + it * 32]);
            v[2 * it] = f.x;
            v[2 * it + 1] = f.y;
            mx = fmaxf(mx, fmaxf(f.x, f.y));
        }
        #pragma unroll
        for (int o = 16; o > 0; o >>= 1) mx = fmaxf(mx, __shfl_xor_sync(0xFFFFFFFFu, mx, o));
        float sum = 0.f;
        #pragma unroll
        for (int it = 0; it < 8; it++) {
            float e0 = __expf(v[2 * it] - mx);
            float e1 = __expf(v[2 * it + 1] - mx);
            e[wid][(lane + it * 32) * 2]     = e0;
            e[wid][(lane + it * 32) * 2 + 1] = e1;
            sum += e0 + e1;
        }
        #pragma unroll
        for (int o = 16; o > 0; o >>= 1) sum += __shfl_xor_sync(0xFFFFFFFFu, sum, o);
        if (lane == 0) winv[wid] = __frcp_rn(sum);
    }
    __syncthreads();

    float* an = attn + (size_t)ng * N_;
    for (int m = tid; m < N_; m += 256) {
        float a = 0.f;
        #pragma unroll
        for (int h = 0; h < H_; h++) a += e[h][m] * winv[h];
        an[m] = a;
    }
}

// ---------------- per-batch top-2 threshold + positions -------------------------
__global__ __launch_bounds__(256) void top2_kernel(
    const float* __restrict__ attn, int* __restrict__ pos, int* __restrict__ cnt)
{
    __shared__ float v1s[256], v2s[256];
    __shared__ float s_kth;
    __shared__ int   s_cnt;

    const int b = blockIdx.x;
    const int tid = threadIdx.x;
    const float* A = attn + (size_t)b * N_ * N_;

    float v1 = -FLT_MAX, v2 = -FLT_MAX;
    for (int i = tid; i < N_ * N_; i += 256) {
        float v = A[i];
        if (v > v1) { v2 = v1; v1 = v; }
        else if (v > v2) v2 = v;
    }
    v1s[tid] = v1; v2s[tid] = v2;
    __syncthreads();
    if (tid == 0) {
        float t1 = -FLT_MAX, t2 = -FLT_MAX;
        for (int i = 0; i < 256; i++) {
            float a = v1s[i], c = v2s[i];
            if (a > t1) { t2 = t1; t1 = a; } else if (a > t2) t2 = a;
            if (c > t1) { t2 = t1; t1 = c; } else if (c > t2) t2 = c;
        }
        s_kth = t2;
        s_cnt = 0;
    }
    __syncthreads();
    const float kth = s_kth;
    const int base = b * MAXP * 2;
    for (int i = tid; i < N_ * N_; i += 256) {
        if (A[i] >= kth) {
            int idx = atomicAdd(&s_cnt, 1);
            if (idx < MAXP) {
                pos[base + idx * 2]     = i >> 9;
                pos[base + idx * 2 + 1] = i & (N_ - 1);
            }
        }
    }
    __syncthreads();
    if (tid == 0) {
        int c = s_cnt < MAXP ? s_cnt : MAXP;
        for (int a2 = 1; a2 < c; a2++) {
            int ki = pos[base + a2 * 2], kj = pos[base + a2 * 2 + 1];
            int key = ki * N_ + kj;
            int p = a2 - 1;
            while (p >= 0) {
                int pi = pos[base + p * 2], pj = pos[base + p * 2 + 1];
                if (pi * N_ + pj <= key) break;
                pos[base + (p + 1) * 2] = pi;
                pos[base + (p + 1) * 2 + 1] = pj;
                p--;
            }
            pos[base + (p + 1) * 2] = ki;
            pos[base + (p + 1) * 2 + 1] = kj;
        }
        cnt[b] = c;
    }
}

// ---------------- sparse adjacency apply + GC epilogue --------------------------
__global__ __launch_bounds__(256) void out_kernel(
    const float* __restrict__ attn, const float* __restrict__ hidden,
    const float* __restrict__ bgc, const int* __restrict__ pos,
    const int* __restrict__ cnt, float* __restrict__ out)
{
    const int b = blockIdx.y;
    const int n = blockIdx.x;
    const int tid = threadIdx.x;

    __shared__ int   s_nc;
    __shared__ int   s_cols[2 * MAXP];
    __shared__ float s_w[2 * MAXP];
    __shared__ float s_wd, s_inv;

    if (tid == 0) {
        const float* An = attn + ((size_t)b * N_ + n) * N_;
        const int base = b * MAXP * 2;
        int c = cnt[b];
        int nc = 0;
        float wd = An[n];
        float sum = wd;
        for (int e = 0; e < c; e++) {
            int i = pos[base + e * 2], j = pos[base + e * 2 + 1];
            if (i == n && j != n) { float w = An[j]; s_cols[nc] = j; s_w[nc] = w; sum += w; nc++; }
            if (j == n && i != n) { float w = An[i]; s_cols[nc] = i; s_w[nc] = w; sum += w; nc++; }
        }
        s_nc = nc; s_wd = wd; s_inv = 1.f / (sum + 1.f);
    }
    __syncthreads();

    const int nc = s_nc;
    const float wd = s_wd, inv = s_inv;
    const float* hn = hidden + ((size_t)b * N_ + n) * D_;
    float* on = out + ((size_t)b * N_ + n) * D_;

    for (int d = tid; d < D_; d += 256) {
        float v = wd * hn[d];
        for (int e = 0; e < nc; e++)
            v += s_w[e] * hidden[((size_t)b * N_ + s_cols[e]) * D_ + d];
        v = v * inv + __ldg(&bgc[d]);
        on[d] = fmaxf(v, 0.f);
    }
}

// ---------------- launch ------------------------------------------------------
extern "C" void kernel_launch(void* const* d_in, const int* in_sizes, int n_in,
                              void* d_out, int out_size)
{
    const float* fuse = (const float*)d_in[0];
    const float* Wq   = (const float*)d_in[1];
    const float* bq   = (const float*)d_in[2];
    const float* Wk   = (const float*)d_in[3];
    const float* bk   = (const float*)d_in[4];
    const float* Wgc  = (const float*)d_in[5];
    const float* bgc  = (const float*)d_in[6];
    float* out = (float*)d_out;

    __half *Ahi, *Bh, *Qhi, *Qlo, *Khi, *S;
    float *q, *k, *hid, *attn;
    int *pos, *cnt;
    cudaGetSymbolAddress((void**)&Ahi,  g_Ahi);
    cudaGetSymbolAddress((void**)&Bh,   g_Bh);
    cudaGetSymbolAddress((void**)&Qhi,  g_Qhi);
    cudaGetSymbolAddress((void**)&Qlo,  g_Qlo);
    cudaGetSymbolAddress((void**)&Khi,  g_Khi);
    cudaGetSymbolAddress((void**)&S,    g_S);
    cudaGetSymbolAddress((void**)&q,    g_q);
    cudaGetSymbolAddress((void**)&k,    g_k);
    cudaGetSymbolAddress((void**)&hid,  g_h);
    cudaGetSymbolAddress((void**)&attn, g_attn);
    cudaGetSymbolAddress((void**)&pos,  g_pos);
    cudaGetSymbolAddress((void**)&cnt,  g_cnt);

    // 0) fp16 conversions: A hi-only (vectorized); B via zero-fill + transpose
    convA_kernel<<<(M_ * KP_ / 4 + 255) / 256, 256>>>(fuse, Ahi);
    zeroB_kernel<<<(NPAD_ * KP_ / 8 + 255) / 256, 256>>>(Bh);
    transB_kernel<<<dim3(KP_ / 32, (D_ + 31) / 32, 3), 256>>>(Wq, Wk, Wgc, Bh);

    // 1) fused HMMA GEMM (hi term only, 2 CTA/SM) -> q, k, hidden
    cudaFuncSetAttribute(gemm_hmma_kernel, cudaFuncAttributeMaxDynamicSharedMemorySize, GEMM_SMEM);
    gemm_hmma_kernel<<<dim3(NPAD_ / 128, M_ / 128), 256, GEMM_SMEM>>>(
        Ahi, Bh, bq, bk, q, k, hid);

    // 2) pack q (hi/lo) and k (hi) head-padded fp16 (vectorized)
    pack_qk_kernel<<<(BHN * 16 + 255) / 256, 256>>>(q, k, Qhi, Qlo, Khi);

    // 3) HMMA score GEMM (2 terms, 2 CTA/SM) -> S[B,H,N,N] fp16
    cudaFuncSetAttribute(score_hmma_kernel, cudaFuncAttributeMaxDynamicSharedMemorySize, SGEMM_SMEM);
    score_hmma_kernel<<<dim3(N_ / 128, N_ / 128, B_ * H_), 256, SGEMM_SMEM>>>(
        Qhi, Qlo, Khi, S);

    // 4) softmax + head-sum -> attn
    softmax_kernel<<<M_, 256>>>(S, attn);

    // 5) per-batch top-2 threshold + sparse positions
    top2_kernel<<<B_, 256>>>(attn, pos, cnt);

    // 6) sparse adjacency apply + graph-conv epilogue
    out_kernel<<<dim3(N_, B_), 256>>>(attn, hid, bgc, pos, cnt, out);
}